// round 10
// baseline (speedup 1.0000x reference)
#include <cuda_runtime.h>
#include <cuda_bf16.h>
#include <cstdint>

// Problem constants (fixed by the dataset)
#define M_ROWS 1024     // B*T_NEW
#define CDIM   2048
#define HHEADS 16
#define DHEAD  128
#define TPAST  2048
#define TNEW   128
#define TTOT   2176
#define BATCH  8

// ---------------------------------------------------------------------------
// Scratch (no cudaMalloc allowed)
// ---------------------------------------------------------------------------
__device__ float g_Q[M_ROWS * CDIM];       // 8 MB
__device__ float g_attn[M_ROWS * CDIM];    // 8 MB (tf32-pre-rounded by attn)
__device__ float g_xr[M_ROWS * CDIM];      // 8 MB  x, tf32-pre-rounded
__device__ float g_WT[4ull * CDIM * CDIM]; // 64 MB Wq/Wk/Wv/Wo transposed+rounded
__device__ float g_Kr[(size_t)BATCH * HHEADS * TTOT * DHEAD];  // 142 MB RNA-rounded K

__device__ __forceinline__ float tf32r(float x) {
    float y;
    asm("cvt.rna.tf32.f32 %0, %1;" : "=f"(y) : "f"(x));
    return y;
}
__device__ __forceinline__ void mma8(float* c, const float* a, const float* b) {
    const uint32_t* A = reinterpret_cast<const uint32_t*>(a);
    const uint32_t* B = reinterpret_cast<const uint32_t*>(b);
    asm volatile(
        "mma.sync.aligned.m16n8k8.row.col.f32.tf32.tf32.f32 "
        "{%0,%1,%2,%3}, {%4,%5,%6,%7}, {%8,%9}, {%0,%1,%2,%3};\n"
        : "+f"(c[0]), "+f"(c[1]), "+f"(c[2]), "+f"(c[3])
        : "r"(A[0]), "r"(A[1]), "r"(A[2]), "r"(A[3]), "r"(B[0]), "r"(B[1]));
}
__device__ __forceinline__ void cp_async16(uint32_t saddr, const void* gaddr) {
    asm volatile("cp.async.ca.shared.global [%0], [%1], 16;\n" :: "r"(saddr), "l"(gaddr));
}
#define SWZ128(o) ((o) ^ (((o) >> 3) & 0x70))

// ---------------------------------------------------------------------------
// Prep kernel: z<4 -> transpose+round W_z into g_WT slab; z==4 -> round x
// ---------------------------------------------------------------------------
__global__ void prep_kernel(
    const float* __restrict__ Wq, const float* __restrict__ Wk,
    const float* __restrict__ Wv, const float* __restrict__ Wo,
    const float* __restrict__ x)
{
    int z = blockIdx.z;
    int tx = threadIdx.x, ty = threadIdx.y;
    if (z == 4) {
        int idx = blockIdx.y * 64 + blockIdx.x;
        if (idx >= 1024) return;
        size_t base = (size_t)idx * 2048 + (ty * 32 + tx) * 8;
        const float4* src = reinterpret_cast<const float4*>(x + base);
        float4* dst = reinterpret_cast<float4*>(g_xr + base);
#pragma unroll
        for (int j = 0; j < 2; j++) {
            float4 v = src[j];
            v.x = tf32r(v.x); v.y = tf32r(v.y); v.z = tf32r(v.z); v.w = tf32r(v.w);
            dst[j] = v;
        }
        return;
    }
    const float* W = (z == 0) ? Wq : (z == 1) ? Wk : (z == 2) ? Wv : Wo;
    float* WT = g_WT + (size_t)z * CDIM * CDIM;
    __shared__ float t[32][33];
    int x0 = blockIdx.x * 32, y0 = blockIdx.y * 32;
#pragma unroll
    for (int j = 0; j < 4; j++)
        t[ty + 8 * j][tx] = tf32r(W[(size_t)(y0 + ty + 8 * j) * CDIM + x0 + tx]);
    __syncthreads();
#pragma unroll
    for (int j = 0; j < 4; j++)
        WT[(size_t)(x0 + ty + 8 * j) * CDIM + y0 + tx] = t[tx][ty + 8 * j];
}

// init out with bias (for split-K reduction epilogue of gemm_wo)
__global__ void init_out(const float* __restrict__ bo, float* __restrict__ out) {
    int i = blockIdx.x * 1024 + threadIdx.x;   // 2048 x 1024 = 2M
    out[i] = bo[i & (CDIM - 1)];
}

// ---------------------------------------------------------------------------
// cp.async 2-stage tf32 GEMM: CTA 128x128, warp 64x32, k-chunk 32.
// ---------------------------------------------------------------------------
#define GSTAGE_FLOATS 8192            // 32 KB per stage (A 4096 + B 4096)
#define GEMM_SMEM_BYTES (2 * GSTAGE_FLOATS * 4)   // 65536

__device__ __forceinline__ void fill_chunk(
    uint32_t sbase, int st, const float* __restrict__ Ap,
    const float* __restrict__ Bp, int kt)
{
    uint32_t base = sbase + st * (GSTAGE_FLOATS * 4);
    int tid = threadIdx.x;
#pragma unroll
    for (int i = 0; i < 4; i++) {
        int f = tid + i * 256;            // 0..1023
        int r = f >> 3, k4 = f & 7;
        uint32_t off = SWZ128((uint32_t)(r * 128 + k4 * 16));
        cp_async16(base + off,         Ap + (size_t)r * CDIM + kt + k4 * 4);
        cp_async16(base + 16384 + off, Bp + (size_t)r * CDIM + kt + k4 * 4);
    }
    asm volatile("cp.async.commit_group;\n");
}

__device__ __forceinline__ void gemm_core(
    const float* __restrict__ Ap, const float* __restrict__ Bp,
    const float* __restrict__ bias, float* __restrict__ out,
    float* __restrict__ outR,   // scatter only: extra RNA-rounded copy (or null)
    int scatter, int bm, int bn, float* smem, int k0, int kch, int red)
{
    int tid = threadIdx.x;
    int lane = tid & 31, wid = tid >> 5;
    int g = lane >> 2, tg = lane & 3;
    int wr = (wid >> 2) * 64;
    int wc = (wid & 3) * 32;
    uint32_t sbase = (uint32_t)__cvta_generic_to_shared(smem);

    float acc[4][4][4];
#pragma unroll
    for (int i = 0; i < 4; i++)
#pragma unroll
        for (int j = 0; j < 4; j++)
#pragma unroll
            for (int k = 0; k < 4; k++) acc[i][j][k] = 0.f;

    fill_chunk(sbase, 0, Ap, Bp, k0);
    fill_chunk(sbase, 1, Ap, Bp, k0 + 32);
    asm volatile("cp.async.wait_group 1;\n");
    __syncthreads();

    int xv = g << 2;

    for (int i = 0; i < kch; i++) {
        int st = i & 1;
        const float* sA = smem + st * GSTAGE_FLOATS;
        const float* sB = sA + 4096;

#pragma unroll
        for (int ks = 0; ks < 4; ks++) {
            int c0 = (ks * 8 + tg) ^ xv;
            int c1 = (ks * 8 + tg + 4) ^ xv;
            float a[4][4];
#pragma unroll
            for (int mi = 0; mi < 4; mi++) {
                int r0 = (wr + mi * 16 + g) * 32;
                int r1 = r0 + 8 * 32;
                a[mi][0] = sA[r0 + c0];
                a[mi][1] = sA[r1 + c0];
                a[mi][2] = sA[r0 + c1];
                a[mi][3] = sA[r1 + c1];
            }
            float b[4][2];
#pragma unroll
            for (int ni = 0; ni < 4; ni++) {
                int rn = (wc + ni * 8 + g) * 32;
                b[ni][0] = sB[rn + c0];
                b[ni][1] = sB[rn + c1];
            }
#pragma unroll
            for (int mi = 0; mi < 4; mi++)
#pragma unroll
                for (int ni = 0; ni < 4; ni++)
                    mma8(acc[mi][ni], a[mi], b[ni]);
        }

        __syncthreads();
        if (i + 2 < kch) fill_chunk(sbase, st, Ap, Bp, k0 + (i + 2) * 32);
        if (i + 1 < kch) {
            if (i + 2 < kch) asm volatile("cp.async.wait_group 1;\n");
            else             asm volatile("cp.async.wait_group 0;\n");
            __syncthreads();
        }
    }

#pragma unroll
    for (int mi = 0; mi < 4; mi++) {
#pragma unroll
        for (int ni = 0; ni < 4; ni++) {
            int row0 = bm + wr + mi * 16 + g;
            int col0 = bn + wc + ni * 8 + 2 * tg;
#pragma unroll
            for (int e = 0; e < 4; e++) {
                int row = row0 + ((e >= 2) ? 8 : 0);
                int col = col0 + (e & 1);
                float v = acc[mi][ni][e];
                if (red) {
                    atomicAdd(&out[(size_t)row * CDIM + col], v);
                } else if (!scatter) {
                    out[(size_t)row * CDIM + col] = v + bias[col];
                } else {
                    int b_ = row >> 7, t_ = row & 127;
                    int h_ = col >> 7, d_ = col & 127;
                    size_t oi = ((size_t)(b_ * HHEADS + h_) * TTOT + TPAST + t_) * DHEAD + d_;
                    float vb = v + bias[col];
                    out[oi] = vb;
                    if (outR) outR[oi] = tf32r(vb);
                }
            }
        }
    }
}

// ---------------------------------------------------------------------------
// Fused: 512 CTAs; role = bid&3 (0=Q,1=K,2=V GEMM, 3=past copy)
// K producers also write RNA-rounded K into g_Kr for the attention kernel.
// ---------------------------------------------------------------------------
__global__ __launch_bounds__(256, 2) void fused_qkv_copy(
    const float* __restrict__ bq, const float* __restrict__ bk, const float* __restrict__ bv,
    const float* __restrict__ Kp, const float* __restrict__ Vp,
    float* __restrict__ gQ, float* __restrict__ Kout, float* __restrict__ Vout)
{
    extern __shared__ __align__(16) float smem[];
    int lin = blockIdx.x;
    int role = lin & 3;
    int t = lin >> 2;  // 0..127

    if (role == 3) {
        const float4* Ks = reinterpret_cast<const float4*>(Kp) + (size_t)t * (TPAST * DHEAD / 4);
        const float4* Vs = reinterpret_cast<const float4*>(Vp) + (size_t)t * (TPAST * DHEAD / 4);
        float4* Kd  = reinterpret_cast<float4*>(Kout) + (size_t)t * (TTOT * DHEAD / 4);
        float4* Vd  = reinterpret_cast<float4*>(Vout) + (size_t)t * (TTOT * DHEAD / 4);
        float4* KRd = reinterpret_cast<float4*>(g_Kr) + (size_t)t * (TTOT * DHEAD / 4);
        for (int i = threadIdx.x; i < TPAST * DHEAD / 4; i += 256) {
            float4 k = Ks[i];
            Kd[i] = k;
            float4 kr;
            kr.x = tf32r(k.x); kr.y = tf32r(k.y); kr.z = tf32r(k.z); kr.w = tf32r(k.w);
            KRd[i] = kr;
            Vd[i] = Vs[i];
        }
        return;
    }

    int bm = (t >> 4) * 128, bn = (t & 15) * 128;
    const float* Ap = g_xr + (size_t)bm * CDIM;
    const float* Bp = g_WT + (size_t)role * CDIM * CDIM + (size_t)bn * CDIM;
    if (role == 0)      gemm_core(Ap, Bp, bq, gQ,   nullptr, 0, bm, bn, smem, 0, 64, 0);
    else if (role == 1) gemm_core(Ap, Bp, bk, Kout, g_Kr,    1, bm, bn, smem, 0, 64, 0);
    else                gemm_core(Ap, Bp, bv, Vout, nullptr, 1, bm, bn, smem, 0, 64, 0);
}

// gemm_wo split-K x2: 256 CTAs; tile = bid>>1, kslice = bid&1; RED.ADD epilogue
__global__ __launch_bounds__(256, 2) void gemm_wo(float* __restrict__ out)
{
    extern __shared__ __align__(16) float smem[];
    int t = blockIdx.x;
    int tile = t >> 1, ksl = t & 1;
    int bm = (tile >> 4) * 128, bn = (tile & 15) * 128;
    gemm_core(g_attn + (size_t)bm * CDIM,
              g_WT + 3ull * CDIM * CDIM + (size_t)bn * CDIM,
              nullptr, out, nullptr, 0, bm, bn, smem, ksl * 1024, 32, 1);
}

// ---------------------------------------------------------------------------
// Flash attention: one CTA per (b,h), 8 warps x 16 query rows.
// K: pre-rounded (g_Kr), pure cp.async, 64-row subtiles double-buffered,
//    always 2 subtiles ahead.  V: raw cp.async, 128-row tile, 1 tile ahead.
// Softmax + PV at 128-key tile granularity (17x), S accumulated over 2
// subtiles in registers.  Uniform wait_group 2 / always-commit discipline.
// smem = sQ(128) + sK0(64) + sK1(64) + sV(128) rows of SMS floats.
// ---------------------------------------------------------------------------
#define SMS 132  // padded row stride (floats)

__global__ __launch_bounds__(256) void attn_kernel(
    const float* __restrict__ Kr, const float* __restrict__ Vc)
{
    extern __shared__ float sm[];
    float* sQ  = sm;                        // 128 rows
    float* sK0 = sm + 128 * SMS;            // 64 rows
    float* sK1 = sm + 192 * SMS;            // 64 rows
    float* sV  = sm + 256 * SMS;            // 128 rows

    int tid = threadIdx.x, lane = tid & 31, wid = tid >> 5;
    int g = lane >> 2, tg = lane & 3;
    int bh = blockIdx.x, b = bh >> 4, h = bh & 15;
    const float qscale = 0.08838834764831845f;  // 1/sqrt(128)

    uint32_t sk0u = (uint32_t)__cvta_generic_to_shared(sK0);
    uint32_t sk1u = (uint32_t)__cvta_generic_to_shared(sK1);
    uint32_t svu  = (uint32_t)__cvta_generic_to_shared(sV);

    const float* Kbh = Kr + (size_t)bh * TTOT * DHEAD;
    const float* Vbh = Vc + (size_t)bh * TTOT * DHEAD;

    int r0 = wid * 16;

    // ---- prologue: issue K(0), K(1), V(0) ----
#pragma unroll
    for (int i = 0; i < 8; i++) {          // K(0): 64 rows
        int f = tid + i * 256;
        int r = f >> 5, c4 = (f & 31) * 4;
        cp_async16(sk0u + (uint32_t)(r * SMS + c4) * 4, &Kbh[(size_t)r * DHEAD + c4]);
    }
    asm volatile("cp.async.commit_group;\n");
#pragma unroll
    for (int i = 0; i < 8; i++) {          // K(1)
        int f = tid + i * 256;
        int r = f >> 5, c4 = (f & 31) * 4;
        cp_async16(sk1u + (uint32_t)(r * SMS + c4) * 4, &Kbh[(size_t)(64 + r) * DHEAD + c4]);
    }
    asm volatile("cp.async.commit_group;\n");
#pragma unroll
    for (int i = 0; i < 16; i++) {         // V(0): 128 rows
        int f = tid + i * 256;
        int r = f >> 5, c4 = (f & 31) * 4;
        cp_async16(svu + (uint32_t)(r * SMS + c4) * 4, &Vbh[(size_t)r * DHEAD + c4]);
    }
    asm volatile("cp.async.commit_group;\n");

    // sQ (scaled, RNA tf32)
#pragma unroll
    for (int i = 0; i < 16; i++) {
        int f = tid + i * 256;
        int r = f >> 5, c4 = (f & 31) * 4;
        float4 v = *reinterpret_cast<const float4*>(
            &g_Q[(size_t)(b * TNEW + r) * CDIM + h * DHEAD + c4]);
        sQ[r * SMS + c4 + 0] = tf32r(v.x * qscale);
        sQ[r * SMS + c4 + 1] = tf32r(v.y * qscale);
        sQ[r * SMS + c4 + 2] = tf32r(v.z * qscale);
        sQ[r * SMS + c4 + 3] = tf32r(v.w * qscale);
    }

    float m0 = -1e30f, m1 = -1e30f, l0 = 0.f, l1 = 0.f;
    float O[16][4], S[16][4];
#pragma unroll
    for (int nt = 0; nt < 16; nt++)
#pragma unroll
        for (int e = 0; e < 4; e++) O[nt][e] = 0.f;

    int srcA = 4 * g + (tg >> 1);
    int srcB = srcA + 2;
    bool oddt = (tg & 1) != 0;

    // ---- main loop over 34 subtiles of 64 keys ----
    for (int s = 0; s < 34; s++) {
        asm volatile("cp.async.wait_group 2;\n");   // K(s) ready
        __syncthreads();

        float* sKc = (s & 1) ? sK1 : sK0;
        int half = (s & 1) * 8;

        // S half = Q K_sub^T
#pragma unroll
        for (int nt = 0; nt < 8; nt++)
#pragma unroll
            for (int e = 0; e < 4; e++) S[half + nt][e] = 0.f;

#pragma unroll
        for (int ks = 0; ks < 16; ks++) {
            float a[4];
            a[0] = sQ[(r0 + g) * SMS + ks * 8 + tg];
            a[1] = sQ[(r0 + g + 8) * SMS + ks * 8 + tg];
            a[2] = sQ[(r0 + g) * SMS + ks * 8 + tg + 4];
            a[3] = sQ[(r0 + g + 8) * SMS + ks * 8 + tg + 4];
#pragma unroll
            for (int nt = 0; nt < 8; nt++) {
                float bb[2];
                bb[0] = sKc[(nt * 8 + g) * SMS + ks * 8 + tg];
                bb[1] = sKc[(nt * 8 + g) * SMS + ks * 8 + tg + 4];
                mma8(S[half + nt], a, bb);
            }
        }

        __syncthreads();   // all warps done reading sK[s&1]

        // K(s+2) prefetch into the freed buffer (always commit)
        if (s + 2 < 34) {
            uint32_t skn = (s & 1) ? sk1u : sk0u;
#pragma unroll
            for (int i = 0; i < 8; i++) {
                int f = tid + i * 256;
                int r = f >> 5, c4 = (f & 31) * 4;
                cp_async16(skn + (uint32_t)(r * SMS + c4) * 4,
                           &Kbh[(size_t)((s + 2) * 64 + r) * DHEAD + c4]);
            }
        }
        asm volatile("cp.async.commit_group;\n");

        if (s & 1) {
            int t = s >> 1;   // tile index 0..16

            // causal mask on the final tile (new keys)
            if (s == 33) {
                int q0 = r0 + g, q1 = q0 + 8;
#pragma unroll
                for (int nt = 0; nt < 16; nt++) {
                    int c0 = nt * 8 + 2 * tg;
                    if (c0 > q0) S[nt][0] = -1e30f;
                    if (c0 + 1 > q0) S[nt][1] = -1e30f;
                    if (c0 > q1) S[nt][2] = -1e30f;
                    if (c0 + 1 > q1) S[nt][3] = -1e30f;
                }
            }

            // online softmax over the 128-key tile
            float mx0 = -1e30f, mx1 = -1e30f;
#pragma unroll
            for (int nt = 0; nt < 16; nt++) {
                mx0 = fmaxf(mx0, fmaxf(S[nt][0], S[nt][1]));
                mx1 = fmaxf(mx1, fmaxf(S[nt][2], S[nt][3]));
            }
            mx0 = fmaxf(mx0, __shfl_xor_sync(0xffffffffu, mx0, 1));
            mx0 = fmaxf(mx0, __shfl_xor_sync(0xffffffffu, mx0, 2));
            mx1 = fmaxf(mx1, __shfl_xor_sync(0xffffffffu, mx1, 1));
            mx1 = fmaxf(mx1, __shfl_xor_sync(0xffffffffu, mx1, 2));

            float mn0 = fmaxf(m0, mx0), mn1 = fmaxf(m1, mx1);
            float sc0 = __expf(m0 - mn0), sc1 = __expf(m1 - mn1);
            float rs0 = 0.f, rs1 = 0.f;
#pragma unroll
            for (int nt = 0; nt < 16; nt++) {
                S[nt][0] = __expf(S[nt][0] - mn0);
                S[nt][1] = __expf(S[nt][1] - mn0);
                S[nt][2] = __expf(S[nt][2] - mn1);
                S[nt][3] = __expf(S[nt][3] - mn1);
                rs0 += S[nt][0] + S[nt][1];
                rs1 += S[nt][2] + S[nt][3];
            }
            rs0 += __shfl_xor_sync(0xffffffffu, rs0, 1);
            rs0 += __shfl_xor_sync(0xffffffffu, rs0, 2);
            rs1 += __shfl_xor_sync(0xffffffffu, rs1, 1);
            rs1 += __shfl_xor_sync(0xffffffffu, rs1, 2);

            l0 = l0 * sc0 + rs0;
            l1 = l1 * sc1 + rs1;
#pragma unroll
            for (int nt = 0; nt < 16; nt++) {
                O[nt][0] *= sc0; O[nt][1] *= sc0;
                O[nt][2] *= sc1; O[nt][3] *= sc1;
            }
            m0 = mn0; m1 = mn1;

            // round P for the MMA
#pragma unroll
            for (int nt = 0; nt < 16; nt++)
#pragma unroll
                for (int e = 0; e < 4; e++) S[nt][e] = tf32r(S[nt][e]);

            asm volatile("cp.async.wait_group 2;\n");   // V(t) ready
            __syncthreads();

            // O += P V over the full 128-key tile
#pragma unroll
            for (int kv = 0; kv < 16; kv++) {
                float e0 = __shfl_sync(0xffffffffu, S[kv][0], srcA);
                float o0 = __shfl_sync(0xffffffffu, S[kv][1], srcA);
                float e1 = __shfl_sync(0xffffffffu, S[kv][2], srcA);
                float o1 = __shfl_sync(0xffffffffu, S[kv][3], srcA);
                float f0 = __shfl_sync(0xffffffffu, S[kv][0], srcB);
                float p0 = __shfl_sync(0xffffffffu, S[kv][1], srcB);
                float f1 = __shfl_sync(0xffffffffu, S[kv][2], srcB);
                float p1 = __shfl_sync(0xffffffffu, S[kv][3], srcB);
                float a[4];
                a[0] = oddt ? o0 : e0;
                a[1] = oddt ? o1 : e1;
                a[2] = oddt ? p0 : f0;
                a[3] = oddt ? p1 : f1;
#pragma unroll
                for (int nt = 0; nt < 16; nt++) {
                    float bb[2];
                    bb[0] = sV[(kv * 8 + tg) * SMS + nt * 8 + g];
                    bb[1] = sV[(kv * 8 + tg + 4) * SMS + nt * 8 + g];
                    mma8(O[nt], a, bb);
                }
            }

            __syncthreads();   // all warps done reading sV

            // V(t+1) prefetch (always commit)
            if (t + 1 < 17) {
#pragma unroll
                for (int i = 0; i < 16; i++) {
                    int f = tid + i * 256;
                    int r = f >> 5, c4 = (f & 31) * 4;
                    cp_async16(svu + (uint32_t)(r * SMS + c4) * 4,
                               &Vbh[(size_t)((t + 1) * 128 + r) * DHEAD + c4]);
                }
            }
            asm volatile("cp.async.commit_group;\n");
        }
    }

    float i0 = 1.f / l0, i1 = 1.f / l1;
#pragma unroll
    for (int nt = 0; nt < 16; nt++) {
        int col = h * DHEAD + nt * 8 + 2 * tg;
        float* o0 = &g_attn[(size_t)(b * TNEW + r0 + g) * CDIM + col];
        o0[0] = tf32r(O[nt][0] * i0);
        o0[1] = tf32r(O[nt][1] * i0);
        float* o1 = &g_attn[(size_t)(b * TNEW + r0 + g + 8) * CDIM + col];
        o1[0] = tf32r(O[nt][2] * i1);
        o1[1] = tf32r(O[nt][3] * i1);
    }
}

// ---------------------------------------------------------------------------
extern "C" void kernel_launch(void* const* d_in, const int* in_sizes, int n_in,
                              void* d_out, int out_size)
{
    const float* x  = (const float*)d_in[0];
    const float* Kp = (const float*)d_in[1];
    const float* Vp = (const float*)d_in[2];
    const float* Wq = (const float*)d_in[3];
    const float* bq = (const float*)d_in[4];
    const float* Wk = (const float*)d_in[5];
    const float* bk = (const float*)d_in[6];
    const float* Wv = (const float*)d_in[7];
    const float* bv = (const float*)d_in[8];
    const float* Wo = (const float*)d_in[9];
    const float* bo = (const float*)d_in[10];

    float* out  = (float*)d_out;
    float* Kout = out + (size_t)M_ROWS * CDIM;
    float* Vout = Kout + (size_t)BATCH * HHEADS * TTOT * DHEAD;

    float *gQ, *gKr;
    cudaGetSymbolAddress((void**)&gQ, g_Q);
    cudaGetSymbolAddress((void**)&gKr, g_Kr);

    const int attn_smem = 384 * SMS * sizeof(float);  // 202,752 B
    cudaFuncSetAttribute(attn_kernel, cudaFuncAttributeMaxDynamicSharedMemorySize, attn_smem);
    cudaFuncSetAttribute(fused_qkv_copy, cudaFuncAttributeMaxDynamicSharedMemorySize, GEMM_SMEM_BYTES);
    cudaFuncSetAttribute(gemm_wo, cudaFuncAttributeMaxDynamicSharedMemorySize, GEMM_SMEM_BYTES);

    // Phase 0: transpose+round weights, round x; init out with bias
    prep_kernel<<<dim3(64, 64, 5), dim3(32, 8)>>>(Wq, Wk, Wv, Wo, x);
    init_out<<<2048, 1024>>>(bo, out);

    // Phase 1: fused QKV GEMMs + past-KV copy (role-interleaved); K producers
    // also write the RNA-rounded K copy used by attention.
    fused_qkv_copy<<<512, 256, GEMM_SMEM_BYTES>>>(bq, bk, bv, Kp, Vp, gQ, Kout, Vout);

    // Phase 2: attention
    attn_kernel<<<BATCH * HHEADS, 256, attn_smem>>>(gKr, Vout);

    // Phase 3: output projection (split-K x2, deterministic RED.ADD)
    gemm_wo<<<256, 256, GEMM_SMEM_BYTES>>>(out);
}

// round 11
// speedup vs baseline: 1.1128x; 1.1128x over previous
#include <cuda_runtime.h>
#include <cuda_bf16.h>
#include <cstdint>

// Problem constants (fixed by the dataset)
#define M_ROWS 1024     // B*T_NEW
#define CDIM   2048
#define HHEADS 16
#define DHEAD  128
#define TPAST  2048
#define TNEW   128
#define TTOT   2176
#define BATCH  8

// ---------------------------------------------------------------------------
// Scratch (no cudaMalloc allowed)
// ---------------------------------------------------------------------------
__device__ float g_Q[M_ROWS * CDIM];       // 8 MB
__device__ float g_attn[M_ROWS * CDIM];    // 8 MB (tf32-pre-rounded by attn)
__device__ float g_xr[M_ROWS * CDIM];      // 8 MB  x, tf32-pre-rounded
__device__ float g_WT[4ull * CDIM * CDIM]; // 64 MB Wq/Wk/Wv/Wo transposed+rounded

__device__ __forceinline__ float tf32r(float x) {
    float y;
    asm("cvt.rna.tf32.f32 %0, %1;" : "=f"(y) : "f"(x));
    return y;
}
__device__ __forceinline__ void mma8(float* c, const float* a, const float* b) {
    const uint32_t* A = reinterpret_cast<const uint32_t*>(a);
    const uint32_t* B = reinterpret_cast<const uint32_t*>(b);
    asm volatile(
        "mma.sync.aligned.m16n8k8.row.col.f32.tf32.tf32.f32 "
        "{%0,%1,%2,%3}, {%4,%5,%6,%7}, {%8,%9}, {%0,%1,%2,%3};\n"
        : "+f"(c[0]), "+f"(c[1]), "+f"(c[2]), "+f"(c[3])
        : "r"(A[0]), "r"(A[1]), "r"(A[2]), "r"(A[3]), "r"(B[0]), "r"(B[1]));
}
__device__ __forceinline__ void cp_async16(uint32_t saddr, const void* gaddr) {
    asm volatile("cp.async.ca.shared.global [%0], [%1], 16;\n" :: "r"(saddr), "l"(gaddr));
}
#define SWZ128(o) ((o) ^ (((o) >> 3) & 0x70))

// ---------------------------------------------------------------------------
// Prep kernel: z<4 -> transpose+round W_z into g_WT slab; z==4 -> round x
// ---------------------------------------------------------------------------
__global__ void prep_kernel(
    const float* __restrict__ Wq, const float* __restrict__ Wk,
    const float* __restrict__ Wv, const float* __restrict__ Wo,
    const float* __restrict__ x)
{
    int z = blockIdx.z;
    int tx = threadIdx.x, ty = threadIdx.y;
    if (z == 4) {
        int idx = blockIdx.y * 64 + blockIdx.x;
        if (idx >= 1024) return;
        size_t base = (size_t)idx * 2048 + (ty * 32 + tx) * 8;
        const float4* src = reinterpret_cast<const float4*>(x + base);
        float4* dst = reinterpret_cast<float4*>(g_xr + base);
#pragma unroll
        for (int j = 0; j < 2; j++) {
            float4 v = src[j];
            v.x = tf32r(v.x); v.y = tf32r(v.y); v.z = tf32r(v.z); v.w = tf32r(v.w);
            dst[j] = v;
        }
        return;
    }
    const float* W = (z == 0) ? Wq : (z == 1) ? Wk : (z == 2) ? Wv : Wo;
    float* WT = g_WT + (size_t)z * CDIM * CDIM;
    __shared__ float t[32][33];
    int x0 = blockIdx.x * 32, y0 = blockIdx.y * 32;
#pragma unroll
    for (int j = 0; j < 4; j++)
        t[ty + 8 * j][tx] = tf32r(W[(size_t)(y0 + ty + 8 * j) * CDIM + x0 + tx]);
    __syncthreads();
#pragma unroll
    for (int j = 0; j < 4; j++)
        WT[(size_t)(x0 + ty + 8 * j) * CDIM + y0 + tx] = t[tx][ty + 8 * j];
}

// init out with bias (for split-K reduction epilogue of gemm_wo)
__global__ void init_out(const float* __restrict__ bo, float* __restrict__ out) {
    int i = blockIdx.x * 1024 + threadIdx.x;   // 2048 x 1024 = 2M
    out[i] = bo[i & (CDIM - 1)];
}

// ---------------------------------------------------------------------------
// cp.async 3-stage tf32 GEMM: CTA 128x128, warp 64x32, k-chunk 32.
// D[m][n] = sum_{k in [k0, k0+kch*32)} Ap[m][k]*Bp[n][k]  (+bias / or RED.ADD)
// smem: 3 stages x 32 KB = 96 KB -> 2 CTAs/SM (192 KB <= 228 KB).
// ---------------------------------------------------------------------------
#define GSTAGE_FLOATS 8192            // 32 KB per stage (A 4096 + B 4096)
#define GEMM_SMEM_BYTES (3 * GSTAGE_FLOATS * 4)   // 98304

__device__ __forceinline__ void fill_chunk(
    uint32_t sbase, int st, const float* __restrict__ Ap,
    const float* __restrict__ Bp, int kt)
{
    uint32_t base = sbase + st * (GSTAGE_FLOATS * 4);
    int tid = threadIdx.x;
#pragma unroll
    for (int i = 0; i < 4; i++) {
        int f = tid + i * 256;            // 0..1023
        int r = f >> 3, k4 = f & 7;
        uint32_t off = SWZ128((uint32_t)(r * 128 + k4 * 16));
        cp_async16(base + off,         Ap + (size_t)r * CDIM + kt + k4 * 4);
        cp_async16(base + 16384 + off, Bp + (size_t)r * CDIM + kt + k4 * 4);
    }
    asm volatile("cp.async.commit_group;\n");
}

__device__ __forceinline__ void gemm_core(
    const float* __restrict__ Ap, const float* __restrict__ Bp,
    const float* __restrict__ bias, float* __restrict__ out,
    int scatter, int bm, int bn, float* smem, int k0, int kch, int red)
{
    int tid = threadIdx.x;
    int lane = tid & 31, wid = tid >> 5;
    int g = lane >> 2, tg = lane & 3;
    int wr = (wid >> 2) * 64;
    int wc = (wid & 3) * 32;
    uint32_t sbase = (uint32_t)__cvta_generic_to_shared(smem);

    float acc[4][4][4];
#pragma unroll
    for (int i = 0; i < 4; i++)
#pragma unroll
        for (int j = 0; j < 4; j++)
#pragma unroll
            for (int k = 0; k < 4; k++) acc[i][j][k] = 0.f;

    fill_chunk(sbase, 0, Ap, Bp, k0);
    fill_chunk(sbase, 1, Ap, Bp, k0 + 32);
    fill_chunk(sbase, 2, Ap, Bp, k0 + 64);
    asm volatile("cp.async.wait_group 2;\n");   // chunk 0 ready
    __syncthreads();

    int xv = g << 2;

    for (int i = 0; i < kch; i++) {
        int st = i % 3;
        const float* sA = smem + st * GSTAGE_FLOATS;
        const float* sB = sA + 4096;

#pragma unroll
        for (int ks = 0; ks < 4; ks++) {
            int c0 = (ks * 8 + tg) ^ xv;
            int c1 = (ks * 8 + tg + 4) ^ xv;
            float a[4][4];
#pragma unroll
            for (int mi = 0; mi < 4; mi++) {
                int r0 = (wr + mi * 16 + g) * 32;
                int r1 = r0 + 8 * 32;
                a[mi][0] = sA[r0 + c0];
                a[mi][1] = sA[r1 + c0];
                a[mi][2] = sA[r0 + c1];
                a[mi][3] = sA[r1 + c1];
            }
            float b[4][2];
#pragma unroll
            for (int ni = 0; ni < 4; ni++) {
                int rn = (wc + ni * 8 + g) * 32;
                b[ni][0] = sB[rn + c0];
                b[ni][1] = sB[rn + c1];
            }
#pragma unroll
            for (int mi = 0; mi < 4; mi++)
#pragma unroll
                for (int ni = 0; ni < 4; ni++)
                    mma8(acc[mi][ni], a[mi], b[ni]);
        }

        __syncthreads();                         // stage st free for refill
        if (i + 3 < kch) fill_chunk(sbase, st, Ap, Bp, k0 + (i + 3) * 32);
        if (i + 1 < kch) {
            if (i + 3 < kch)      asm volatile("cp.async.wait_group 2;\n");
            else if (i + 2 < kch) asm volatile("cp.async.wait_group 1;\n");
            else                  asm volatile("cp.async.wait_group 0;\n");
            __syncthreads();
        }
    }

#pragma unroll
    for (int mi = 0; mi < 4; mi++) {
#pragma unroll
        for (int ni = 0; ni < 4; ni++) {
            int row0 = bm + wr + mi * 16 + g;
            int col0 = bn + wc + ni * 8 + 2 * tg;
#pragma unroll
            for (int e = 0; e < 4; e++) {
                int row = row0 + ((e >= 2) ? 8 : 0);
                int col = col0 + (e & 1);
                float v = acc[mi][ni][e];
                if (red) {
                    atomicAdd(&out[(size_t)row * CDIM + col], v);
                } else if (!scatter) {
                    out[(size_t)row * CDIM + col] = v + bias[col];
                } else {
                    int b_ = row >> 7, t_ = row & 127;
                    int h_ = col >> 7, d_ = col & 127;
                    out[((size_t)(b_ * HHEADS + h_) * TTOT + TPAST + t_) * DHEAD + d_] = v + bias[col];
                }
            }
        }
    }
}

// ---------------------------------------------------------------------------
// Fused: 512 CTAs; role = bid&3 (0=Q,1=K,2=V GEMM, 3=past copy)
// ---------------------------------------------------------------------------
__global__ __launch_bounds__(256, 2) void fused_qkv_copy(
    const float* __restrict__ bq, const float* __restrict__ bk, const float* __restrict__ bv,
    const float* __restrict__ Kp, const float* __restrict__ Vp,
    float* __restrict__ gQ, float* __restrict__ Kout, float* __restrict__ Vout)
{
    extern __shared__ __align__(16) float smem[];
    int lin = blockIdx.x;
    int role = lin & 3;
    int t = lin >> 2;  // 0..127

    if (role == 3) {
        const float4* Ks = reinterpret_cast<const float4*>(Kp) + (size_t)t * (TPAST * DHEAD / 4);
        const float4* Vs = reinterpret_cast<const float4*>(Vp) + (size_t)t * (TPAST * DHEAD / 4);
        float4* Kd = reinterpret_cast<float4*>(Kout) + (size_t)t * (TTOT * DHEAD / 4);
        float4* Vd = reinterpret_cast<float4*>(Vout) + (size_t)t * (TTOT * DHEAD / 4);
        for (int i = threadIdx.x; i < TPAST * DHEAD / 4; i += 256) {
            Kd[i] = Ks[i];
            Vd[i] = Vs[i];
        }
        return;
    }

    int bm = (t >> 4) * 128, bn = (t & 15) * 128;
    const float* Ap = g_xr + (size_t)bm * CDIM;
    const float* Bp = g_WT + (size_t)role * CDIM * CDIM + (size_t)bn * CDIM;
    if (role == 0)      gemm_core(Ap, Bp, bq, gQ,   0, bm, bn, smem, 0, 64, 0);
    else if (role == 1) gemm_core(Ap, Bp, bk, Kout, 1, bm, bn, smem, 0, 64, 0);
    else                gemm_core(Ap, Bp, bv, Vout, 1, bm, bn, smem, 0, 64, 0);
}

// gemm_wo split-K x2: 256 CTAs; tile = bid>>1, kslice = bid&1; RED.ADD epilogue
__global__ __launch_bounds__(256, 2) void gemm_wo(float* __restrict__ out)
{
    extern __shared__ __align__(16) float smem[];
    int t = blockIdx.x;
    int tile = t >> 1, ksl = t & 1;
    int bm = (tile >> 4) * 128, bn = (tile & 15) * 128;
    gemm_core(g_attn + (size_t)bm * CDIM,
              g_WT + 3ull * CDIM * CDIM + (size_t)bn * CDIM,
              nullptr, out, 0, bm, bn, smem, ksl * 1024, 32, 1);
}

// ---------------------------------------------------------------------------
// Flash attention (R8 version, best measured): one CTA per (b,h), 8 warps x
// 16 query rows.  K: 64-row subtiles double-buffered, register-staged
// (LDG -> RNA cvt -> STS) under compute.  V: cp.async, 1 tile ahead.
// P in registers via shuffles.  Softmax per 64-key slab.
// smem = sQ(128) + sK0(64) + sK1(64) + sV(128) rows of SMS floats.
// ---------------------------------------------------------------------------
#define SMS 132  // padded row stride (floats)

__global__ __launch_bounds__(256) void attn_kernel(
    const float* __restrict__ Kc, const float* __restrict__ Vc)
{
    extern __shared__ float sm[];
    float* sQ  = sm;                        // 128 rows
    float* sK0 = sm + 128 * SMS;            // 64 rows
    float* sK1 = sm + 192 * SMS;            // 64 rows
    float* sV  = sm + 256 * SMS;            // 128 rows

    int tid = threadIdx.x, lane = tid & 31, wid = tid >> 5;
    int g = lane >> 2, tg = lane & 3;
    int bh = blockIdx.x, b = bh >> 4, h = bh & 15;
    const float qscale = 0.08838834764831845f;  // 1/sqrt(128)

    uint32_t svu = (uint32_t)__cvta_generic_to_shared(sV);

    const float* Kbh = Kc + (size_t)bh * TTOT * DHEAD;
    const float* Vbh = Vc + (size_t)bh * TTOT * DHEAD;

    int r0 = wid * 16;

    // ---- prologue ----
#pragma unroll
    for (int i = 0; i < 16; i++) {
        int f = tid + i * 256;
        int r = f >> 5, c4 = (f & 31) * 4;
        float4 v = *reinterpret_cast<const float4*>(
            &g_Q[(size_t)(b * TNEW + r) * CDIM + h * DHEAD + c4]);
        sQ[r * SMS + c4 + 0] = tf32r(v.x * qscale);
        sQ[r * SMS + c4 + 1] = tf32r(v.y * qscale);
        sQ[r * SMS + c4 + 2] = tf32r(v.z * qscale);
        sQ[r * SMS + c4 + 3] = tf32r(v.w * qscale);
    }

    float4 rk[8];
    // LDG K(0)
#pragma unroll
    for (int i = 0; i < 8; i++) {
        int f = tid + i * 256;
        int r = f >> 5, c4 = (f & 31) * 4;
        rk[i] = *reinterpret_cast<const float4*>(&Kbh[(size_t)r * DHEAD + c4]);
    }
    // V(0) prefetch
#pragma unroll
    for (int i = 0; i < 16; i++) {
        int f = tid + i * 256;
        int r = f >> 5, c4 = (f & 31) * 4;
        cp_async16(svu + (uint32_t)(r * SMS + c4) * 4, &Vbh[(size_t)r * DHEAD + c4]);
    }
    asm volatile("cp.async.commit_group;\n");
    // STS K(0) -> sK0 (RNA)
#pragma unroll
    for (int i = 0; i < 8; i++) {
        int f = tid + i * 256;
        int r = f >> 5, c4 = (f & 31) * 4;
        float4 v;
        v.x = tf32r(rk[i].x); v.y = tf32r(rk[i].y);
        v.z = tf32r(rk[i].z); v.w = tf32r(rk[i].w);
        *reinterpret_cast<float4*>(&sK0[r * SMS + c4]) = v;
    }
    // LDG K(1)
#pragma unroll
    for (int i = 0; i < 8; i++) {
        int f = tid + i * 256;
        int r = f >> 5, c4 = (f & 31) * 4;
        rk[i] = *reinterpret_cast<const float4*>(&Kbh[(size_t)(64 + r) * DHEAD + c4]);
    }

    float m0 = -1e30f, m1 = -1e30f, l0 = 0.f, l1 = 0.f;
    float O[16][4];
#pragma unroll
    for (int nt = 0; nt < 16; nt++)
#pragma unroll
        for (int e = 0; e < 4; e++) O[nt][e] = 0.f;

    int srcA = 4 * g + (tg >> 1);
    int srcB = srcA + 2;
    bool oddt = (tg & 1) != 0;

    // ---- main loop over 34 subtiles of 64 keys ----
    for (int s = 0; s < 34; s++) {
        float* sKc = (s & 1) ? sK1 : sK0;

        // STS K(s+1) into the other buffer
        if (s < 33) {
            float* sKn = (s & 1) ? sK0 : sK1;
#pragma unroll
            for (int i = 0; i < 8; i++) {
                int f = tid + i * 256;
                int r = f >> 5, c4 = (f & 31) * 4;
                float4 v;
                v.x = tf32r(rk[i].x); v.y = tf32r(rk[i].y);
                v.z = tf32r(rk[i].z); v.w = tf32r(rk[i].w);
                *reinterpret_cast<float4*>(&sKn[r * SMS + c4]) = v;
            }
        }
        // LDG K(s+2)
        if (s < 32) {
#pragma unroll
            for (int i = 0; i < 8; i++) {
                int f = tid + i * 256;
                int r = f >> 5, c4 = (f & 31) * 4;
                rk[i] = *reinterpret_cast<const float4*>(
                    &Kbh[(size_t)((s + 2) * 64 + r) * DHEAD + c4]);
            }
        }
        if ((s & 1) == 0) asm volatile("cp.async.wait_group 0;\n");  // V(s/2) ready
        __syncthreads();

        // S = Q K_sub^T  (16 rows x 64 keys per warp)
        float S[8][4];
#pragma unroll
        for (int nt = 0; nt < 8; nt++)
#pragma unroll
            for (int e = 0; e < 4; e++) S[nt][e] = 0.f;

#pragma unroll
        for (int ks = 0; ks < 16; ks++) {
            float a[4];
            a[0] = sQ[(r0 + g) * SMS + ks * 8 + tg];
            a[1] = sQ[(r0 + g + 8) * SMS + ks * 8 + tg];
            a[2] = sQ[(r0 + g) * SMS + ks * 8 + tg + 4];
            a[3] = sQ[(r0 + g + 8) * SMS + ks * 8 + tg + 4];
#pragma unroll
            for (int nt = 0; nt < 8; nt++) {
                float bb[2];
                bb[0] = sKc[(nt * 8 + g) * SMS + ks * 8 + tg];
                bb[1] = sKc[(nt * 8 + g) * SMS + ks * 8 + tg + 4];
                mma8(S[nt], a, bb);
            }
        }

        // causal mask (new keys live in subtiles 32,33)
        if (s >= 32) {
            int cb = (s - 32) * 64;
            int q0 = r0 + g, q1 = q0 + 8;
#pragma unroll
            for (int nt = 0; nt < 8; nt++) {
                int c0 = cb + nt * 8 + 2 * tg;
                if (c0 > q0) S[nt][0] = -1e30f;
                if (c0 + 1 > q0) S[nt][1] = -1e30f;
                if (c0 > q1) S[nt][2] = -1e30f;
                if (c0 + 1 > q1) S[nt][3] = -1e30f;
            }
        }

        // online softmax over this 64-key slab
        float mx0 = -1e30f, mx1 = -1e30f;
#pragma unroll
        for (int nt = 0; nt < 8; nt++) {
            mx0 = fmaxf(mx0, fmaxf(S[nt][0], S[nt][1]));
            mx1 = fmaxf(mx1, fmaxf(S[nt][2], S[nt][3]));
        }
        mx0 = fmaxf(mx0, __shfl_xor_sync(0xffffffffu, mx0, 1));
        mx0 = fmaxf(mx0, __shfl_xor_sync(0xffffffffu, mx0, 2));
        mx1 = fmaxf(mx1, __shfl_xor_sync(0xffffffffu, mx1, 1));
        mx1 = fmaxf(mx1, __shfl_xor_sync(0xffffffffu, mx1, 2));

        float mn0 = fmaxf(m0, mx0), mn1 = fmaxf(m1, mx1);
        float sc0 = __expf(m0 - mn0), sc1 = __expf(m1 - mn1);
        float rs0 = 0.f, rs1 = 0.f;
#pragma unroll
        for (int nt = 0; nt < 8; nt++) {
            S[nt][0] = __expf(S[nt][0] - mn0);
            S[nt][1] = __expf(S[nt][1] - mn0);
            S[nt][2] = __expf(S[nt][2] - mn1);
            S[nt][3] = __expf(S[nt][3] - mn1);
            rs0 += S[nt][0] + S[nt][1];
            rs1 += S[nt][2] + S[nt][3];
        }
        rs0 += __shfl_xor_sync(0xffffffffu, rs0, 1);
        rs0 += __shfl_xor_sync(0xffffffffu, rs0, 2);
        rs1 += __shfl_xor_sync(0xffffffffu, rs1, 1);
        rs1 += __shfl_xor_sync(0xffffffffu, rs1, 2);

        l0 = l0 * sc0 + rs0;
        l1 = l1 * sc1 + rs1;
#pragma unroll
        for (int nt = 0; nt < 16; nt++) {
            O[nt][0] *= sc0; O[nt][1] *= sc0;
            O[nt][2] *= sc1; O[nt][3] *= sc1;
        }
        m0 = mn0; m1 = mn1;

        // round P for the MMA
#pragma unroll
        for (int nt = 0; nt < 8; nt++)
#pragma unroll
            for (int e = 0; e < 4; e++) S[nt][e] = tf32r(S[nt][e]);

        // O += P V : P acc-fragments -> A-fragments via shuffles
        int vrow0 = (s & 1) * 64;
#pragma unroll
        for (int kv = 0; kv < 8; kv++) {
            float e0 = __shfl_sync(0xffffffffu, S[kv][0], srcA);
            float o0 = __shfl_sync(0xffffffffu, S[kv][1], srcA);
            float e1 = __shfl_sync(0xffffffffu, S[kv][2], srcA);
            float o1 = __shfl_sync(0xffffffffu, S[kv][3], srcA);
            float f0 = __shfl_sync(0xffffffffu, S[kv][0], srcB);
            float p0 = __shfl_sync(0xffffffffu, S[kv][1], srcB);
            float f1 = __shfl_sync(0xffffffffu, S[kv][2], srcB);
            float p1 = __shfl_sync(0xffffffffu, S[kv][3], srcB);
            float a[4];
            a[0] = oddt ? o0 : e0;
            a[1] = oddt ? o1 : e1;
            a[2] = oddt ? p0 : f0;
            a[3] = oddt ? p1 : f1;
#pragma unroll
            for (int nt = 0; nt < 16; nt++) {
                float bb[2];
                bb[0] = sV[(vrow0 + kv * 8 + tg) * SMS + nt * 8 + g];
                bb[1] = sV[(vrow0 + kv * 8 + tg + 4) * SMS + nt * 8 + g];
                mma8(O[nt], a, bb);
            }
        }

        __syncthreads();  // all warps done with sK[s&1] and (if s odd) sV

        // refill V for the next tile-pair
        if ((s & 1) == 1 && s < 33) {
            int vt = (s >> 1) + 1;
#pragma unroll
            for (int i = 0; i < 16; i++) {
                int f = tid + i * 256;
                int r = f >> 5, c4 = (f & 31) * 4;
                cp_async16(svu + (uint32_t)(r * SMS + c4) * 4,
                           &Vbh[(size_t)(vt * 128 + r) * DHEAD + c4]);
            }
            asm volatile("cp.async.commit_group;\n");
        }
    }

    float i0 = 1.f / l0, i1 = 1.f / l1;
#pragma unroll
    for (int nt = 0; nt < 16; nt++) {
        int col = h * DHEAD + nt * 8 + 2 * tg;
        float* o0 = &g_attn[(size_t)(b * TNEW + r0 + g) * CDIM + col];
        o0[0] = tf32r(O[nt][0] * i0);
        o0[1] = tf32r(O[nt][1] * i0);
        float* o1 = &g_attn[(size_t)(b * TNEW + r0 + g + 8) * CDIM + col];
        o1[0] = tf32r(O[nt][2] * i1);
        o1[1] = tf32r(O[nt][3] * i1);
    }
}

// ---------------------------------------------------------------------------
extern "C" void kernel_launch(void* const* d_in, const int* in_sizes, int n_in,
                              void* d_out, int out_size)
{
    const float* x  = (const float*)d_in[0];
    const float* Kp = (const float*)d_in[1];
    const float* Vp = (const float*)d_in[2];
    const float* Wq = (const float*)d_in[3];
    const float* bq = (const float*)d_in[4];
    const float* Wk = (const float*)d_in[5];
    const float* bk = (const float*)d_in[6];
    const float* Wv = (const float*)d_in[7];
    const float* bv = (const float*)d_in[8];
    const float* Wo = (const float*)d_in[9];
    const float* bo = (const float*)d_in[10];

    float* out  = (float*)d_out;
    float* Kout = out + (size_t)M_ROWS * CDIM;
    float* Vout = Kout + (size_t)BATCH * HHEADS * TTOT * DHEAD;

    float* gQ;
    cudaGetSymbolAddress((void**)&gQ, g_Q);

    const int attn_smem = 384 * SMS * sizeof(float);  // 202,752 B
    cudaFuncSetAttribute(attn_kernel, cudaFuncAttributeMaxDynamicSharedMemorySize, attn_smem);
    cudaFuncSetAttribute(fused_qkv_copy, cudaFuncAttributeMaxDynamicSharedMemorySize, GEMM_SMEM_BYTES);
    cudaFuncSetAttribute(gemm_wo, cudaFuncAttributeMaxDynamicSharedMemorySize, GEMM_SMEM_BYTES);

    // Phase 0: transpose+round weights, round x; init out with bias
    prep_kernel<<<dim3(64, 64, 5), dim3(32, 8)>>>(Wq, Wk, Wv, Wo, x);
    init_out<<<2048, 1024>>>(bo, out);

    // Phase 1: fused QKV GEMMs + past-KV copy (role-interleaved)
    fused_qkv_copy<<<512, 256, GEMM_SMEM_BYTES>>>(bq, bk, bv, Kp, Vp, gQ, Kout, Vout);

    // Phase 2: attention
    attn_kernel<<<BATCH * HHEADS, 256, attn_smem>>>(Kout, Vout);

    // Phase 3: output projection (split-K x2, deterministic RED.ADD)
    gemm_wo<<<256, 256, GEMM_SMEM_BYTES>>>(out);
}

// round 14
// speedup vs baseline: 1.2027x; 1.0808x over previous
#include <cuda_runtime.h>
#include <cuda_bf16.h>
#include <cstdint>

// Problem constants (fixed by the dataset)
#define M_ROWS 1024     // B*T_NEW
#define CDIM   2048
#define HHEADS 16
#define DHEAD  128
#define TPAST  2048
#define TNEW   128
#define TTOT   2176
#define BATCH  8

// ---------------------------------------------------------------------------
// Scratch (no cudaMalloc allowed)
// ---------------------------------------------------------------------------
__device__ float g_Q[M_ROWS * CDIM];       // 8 MB
__device__ float g_attn[M_ROWS * CDIM];    // 8 MB (tf32-pre-rounded by attn)
__device__ float g_xr[M_ROWS * CDIM];      // 8 MB  x, tf32-pre-rounded
__device__ float g_WT[4ull * CDIM * CDIM]; // 64 MB Wq/Wk/Wv/Wo transposed+rounded

__device__ __forceinline__ float tf32r(float x) {
    float y;
    asm("cvt.rna.tf32.f32 %0, %1;" : "=f"(y) : "f"(x));
    return y;
}
__device__ __forceinline__ void mma8(float* c, const float* a, const float* b) {
    const uint32_t* A = reinterpret_cast<const uint32_t*>(a);
    const uint32_t* B = reinterpret_cast<const uint32_t*>(b);
    asm volatile(
        "mma.sync.aligned.m16n8k8.row.col.f32.tf32.tf32.f32 "
        "{%0,%1,%2,%3}, {%4,%5,%6,%7}, {%8,%9}, {%0,%1,%2,%3};\n"
        : "+f"(c[0]), "+f"(c[1]), "+f"(c[2]), "+f"(c[3])
        : "r"(A[0]), "r"(A[1]), "r"(A[2]), "r"(A[3]), "r"(B[0]), "r"(B[1]));
}
__device__ __forceinline__ void cp_async16(uint32_t saddr, const void* gaddr) {
    asm volatile("cp.async.ca.shared.global [%0], [%1], 16;\n" :: "r"(saddr), "l"(gaddr));
}
#define SWZ128(o) ((o) ^ (((o) >> 3) & 0x70))

// ---------------------------------------------------------------------------
// Prep kernel: z<4 -> transpose+round W_z into g_WT slab; z==4 -> round x;
// z==5 -> init out with bias (for split-K RED.ADD epilogue of gemm_wo)
// grid (64,64,6), block (32,8)
// ---------------------------------------------------------------------------
__global__ void prep_kernel(
    const float* __restrict__ Wq, const float* __restrict__ Wk,
    const float* __restrict__ Wv, const float* __restrict__ Wo,
    const float* __restrict__ x, const float* __restrict__ bo,
    float* __restrict__ out)
{
    int z = blockIdx.z;
    int tx = threadIdx.x, ty = threadIdx.y;
    if (z >= 4) {
        int idx = blockIdx.y * 64 + blockIdx.x;
        if (idx >= 1024) return;
        size_t base = (size_t)idx * 2048 + (ty * 32 + tx) * 8;
        if (z == 4) {
            const float4* src = reinterpret_cast<const float4*>(x + base);
            float4* dst = reinterpret_cast<float4*>(g_xr + base);
#pragma unroll
            for (int j = 0; j < 2; j++) {
                float4 v = src[j];
                v.x = tf32r(v.x); v.y = tf32r(v.y); v.z = tf32r(v.z); v.w = tf32r(v.w);
                dst[j] = v;
            }
        } else {
            // init out with bias
            const float4* bsrc = reinterpret_cast<const float4*>(bo + (base & (CDIM - 1)));
            float4* dst = reinterpret_cast<float4*>(out + base);
#pragma unroll
            for (int j = 0; j < 2; j++) dst[j] = bsrc[j];
        }
        return;
    }
    const float* W = (z == 0) ? Wq : (z == 1) ? Wk : (z == 2) ? Wv : Wo;
    float* WT = g_WT + (size_t)z * CDIM * CDIM;
    __shared__ float t[32][33];
    int x0 = blockIdx.x * 32, y0 = blockIdx.y * 32;
#pragma unroll
    for (int j = 0; j < 4; j++)
        t[ty + 8 * j][tx] = tf32r(W[(size_t)(y0 + ty + 8 * j) * CDIM + x0 + tx]);
    __syncthreads();
#pragma unroll
    for (int j = 0; j < 4; j++)
        WT[(size_t)(x0 + ty + 8 * j) * CDIM + y0 + tx] = t[tx][ty + 8 * j];
}

// ---------------------------------------------------------------------------
// cp.async 2-stage tf32 GEMM (R8 config, best measured): CTA 128x128,
// warp 64x32, k-chunk 32.  smem: 2 stages x 32 KB = 64 KB -> 2 CTAs/SM.
// ---------------------------------------------------------------------------
#define GSTAGE_FLOATS 8192            // 32 KB per stage (A 4096 + B 4096)
#define GEMM_SMEM_BYTES (2 * GSTAGE_FLOATS * 4)   // 65536

__device__ __forceinline__ void fill_chunk(
    uint32_t sbase, int st, const float* __restrict__ Ap,
    const float* __restrict__ Bp, int kt)
{
    uint32_t base = sbase + st * (GSTAGE_FLOATS * 4);
    int tid = threadIdx.x;
#pragma unroll
    for (int i = 0; i < 4; i++) {
        int f = tid + i * 256;            // 0..1023
        int r = f >> 3, k4 = f & 7;
        uint32_t off = SWZ128((uint32_t)(r * 128 + k4 * 16));
        cp_async16(base + off,         Ap + (size_t)r * CDIM + kt + k4 * 4);
        cp_async16(base + 16384 + off, Bp + (size_t)r * CDIM + kt + k4 * 4);
    }
    asm volatile("cp.async.commit_group;\n");
}

__device__ __forceinline__ void gemm_core(
    const float* __restrict__ Ap, const float* __restrict__ Bp,
    const float* __restrict__ bias, float* __restrict__ out,
    int scatter, int bm, int bn, float* smem, int k0, int kch, int red)
{
    int tid = threadIdx.x;
    int lane = tid & 31, wid = tid >> 5;
    int g = lane >> 2, tg = lane & 3;
    int wr = (wid >> 2) * 64;
    int wc = (wid & 3) * 32;
    uint32_t sbase = (uint32_t)__cvta_generic_to_shared(smem);

    float acc[4][4][4];
#pragma unroll
    for (int i = 0; i < 4; i++)
#pragma unroll
        for (int j = 0; j < 4; j++)
#pragma unroll
            for (int k = 0; k < 4; k++) acc[i][j][k] = 0.f;

    fill_chunk(sbase, 0, Ap, Bp, k0);
    fill_chunk(sbase, 1, Ap, Bp, k0 + 32);
    asm volatile("cp.async.wait_group 1;\n");
    __syncthreads();

    int xv = g << 2;

    for (int i = 0; i < kch; i++) {
        int st = i & 1;
        const float* sA = smem + st * GSTAGE_FLOATS;
        const float* sB = sA + 4096;

#pragma unroll
        for (int ks = 0; ks < 4; ks++) {
            int c0 = (ks * 8 + tg) ^ xv;
            int c1 = (ks * 8 + tg + 4) ^ xv;
            float a[4][4];
#pragma unroll
            for (int mi = 0; mi < 4; mi++) {
                int r0 = (wr + mi * 16 + g) * 32;
                int r1 = r0 + 8 * 32;
                a[mi][0] = sA[r0 + c0];
                a[mi][1] = sA[r1 + c0];
                a[mi][2] = sA[r0 + c1];
                a[mi][3] = sA[r1 + c1];
            }
            float b[4][2];
#pragma unroll
            for (int ni = 0; ni < 4; ni++) {
                int rn = (wc + ni * 8 + g) * 32;
                b[ni][0] = sB[rn + c0];
                b[ni][1] = sB[rn + c1];
            }
#pragma unroll
            for (int mi = 0; mi < 4; mi++)
#pragma unroll
                for (int ni = 0; ni < 4; ni++)
                    mma8(acc[mi][ni], a[mi], b[ni]);
        }

        __syncthreads();
        if (i + 2 < kch) fill_chunk(sbase, st, Ap, Bp, k0 + (i + 2) * 32);
        if (i + 1 < kch) {
            if (i + 2 < kch) asm volatile("cp.async.wait_group 1;\n");
            else             asm volatile("cp.async.wait_group 0;\n");
            __syncthreads();
        }
    }

#pragma unroll
    for (int mi = 0; mi < 4; mi++) {
#pragma unroll
        for (int ni = 0; ni < 4; ni++) {
            int row0 = bm + wr + mi * 16 + g;
            int col0 = bn + wc + ni * 8 + 2 * tg;
#pragma unroll
            for (int e = 0; e < 4; e++) {
                int row = row0 + ((e >= 2) ? 8 : 0);
                int col = col0 + (e & 1);
                float v = acc[mi][ni][e];
                if (red) {
                    atomicAdd(&out[(size_t)row * CDIM + col], v);
                } else if (!scatter) {
                    out[(size_t)row * CDIM + col] = v + bias[col];
                } else {
                    int b_ = row >> 7, t_ = row & 127;
                    int h_ = col >> 7, d_ = col & 127;
                    out[((size_t)(b_ * HHEADS + h_) * TTOT + TPAST + t_) * DHEAD + d_] = v + bias[col];
                }
            }
        }
    }
}

// ---------------------------------------------------------------------------
// Fused: 512 CTAs; role = bid&3 (0=Q,1=K,2=V GEMM, 3=past copy)
// ---------------------------------------------------------------------------
__global__ __launch_bounds__(256, 2) void fused_qkv_copy(
    const float* __restrict__ bq, const float* __restrict__ bk, const float* __restrict__ bv,
    const float* __restrict__ Kp, const float* __restrict__ Vp,
    float* __restrict__ gQ, float* __restrict__ Kout, float* __restrict__ Vout)
{
    extern __shared__ __align__(16) float smem[];
    int lin = blockIdx.x;
    int role = lin & 3;
    int t = lin >> 2;  // 0..127

    if (role == 3) {
        const float4* Ks = reinterpret_cast<const float4*>(Kp) + (size_t)t * (TPAST * DHEAD / 4);
        const float4* Vs = reinterpret_cast<const float4*>(Vp) + (size_t)t * (TPAST * DHEAD / 4);
        float4* Kd = reinterpret_cast<float4*>(Kout) + (size_t)t * (TTOT * DHEAD / 4);
        float4* Vd = reinterpret_cast<float4*>(Vout) + (size_t)t * (TTOT * DHEAD / 4);
        for (int i = threadIdx.x; i < TPAST * DHEAD / 4; i += 256) {
            Kd[i] = Ks[i];
            Vd[i] = Vs[i];
        }
        return;
    }

    int bm = (t >> 4) * 128, bn = (t & 15) * 128;
    const float* Ap = g_xr + (size_t)bm * CDIM;
    const float* Bp = g_WT + (size_t)role * CDIM * CDIM + (size_t)bn * CDIM;
    if (role == 0)      gemm_core(Ap, Bp, bq, gQ,   0, bm, bn, smem, 0, 64, 0);
    else if (role == 1) gemm_core(Ap, Bp, bk, Kout, 1, bm, bn, smem, 0, 64, 0);
    else                gemm_core(Ap, Bp, bv, Vout, 1, bm, bn, smem, 0, 64, 0);
}

// gemm_wo split-K x2: 256 CTAs; tile = bid>>1, kslice = bid&1; RED.ADD epilogue
__global__ __launch_bounds__(256, 2) void gemm_wo(float* __restrict__ out)
{
    extern __shared__ __align__(16) float smem[];
    int t = blockIdx.x;
    int tile = t >> 1, ksl = t & 1;
    int bm = (tile >> 4) * 128, bn = (tile & 15) * 128;
    gemm_core(g_attn + (size_t)bm * CDIM,
              g_WT + 3ull * CDIM * CDIM + (size_t)bn * CDIM,
              nullptr, out, 0, bm, bn, smem, ksl * 1024, 32, 1);
}

// ---------------------------------------------------------------------------
// Flash attention (R8 schedule): one CTA per (b,h), 8 warps x 16 query rows.
// K: 64-row subtiles double-buffered, register-staged (LDG -> RNA -> STS).
// V: cp.async (raw), 1 tile ahead, stride SVS=136 -> PV B-loads hit banks
//    8*tg+g (all 32 distinct, conflict-free; 132 gave 2-way conflicts).
// P in registers via shuffles.  Softmax per 64-key slab.
// smem = sQ(128)+sK0(64)+sK1(64) @132 + sV(128) @136.
// ---------------------------------------------------------------------------
#define SMS 132  // sQ/sK row stride (floats): S-phase banks 4g+tg, conflict-free
#define SVS 136  // sV row stride (floats): PV-phase banks 8tg+g, conflict-free
#define ATTN_SMEM_BYTES ((256 * SMS + 128 * SVS) * 4)   // 204800

__global__ __launch_bounds__(256) void attn_kernel(
    const float* __restrict__ Kc, const float* __restrict__ Vc)
{
    extern __shared__ float sm[];
    float* sQ  = sm;                        // 128 rows @ SMS
    float* sK0 = sm + 128 * SMS;            // 64 rows @ SMS
    float* sK1 = sm + 192 * SMS;            // 64 rows @ SMS
    float* sV  = sm + 256 * SMS;            // 128 rows @ SVS

    int tid = threadIdx.x, lane = tid & 31, wid = tid >> 5;
    int g = lane >> 2, tg = lane & 3;
    int bh = blockIdx.x, b = bh >> 4, h = bh & 15;
    const float qscale = 0.08838834764831845f;  // 1/sqrt(128)

    uint32_t svu = (uint32_t)__cvta_generic_to_shared(sV);

    const float* Kbh = Kc + (size_t)bh * TTOT * DHEAD;
    const float* Vbh = Vc + (size_t)bh * TTOT * DHEAD;

    int r0 = wid * 16;

    // ---- prologue ----
#pragma unroll
    for (int i = 0; i < 16; i++) {
        int f = tid + i * 256;
        int r = f >> 5, c4 = (f & 31) * 4;
        float4 v = *reinterpret_cast<const float4*>(
            &g_Q[(size_t)(b * TNEW + r) * CDIM + h * DHEAD + c4]);
        sQ[r * SMS + c4 + 0] = tf32r(v.x * qscale);
        sQ[r * SMS + c4 + 1] = tf32r(v.y * qscale);
        sQ[r * SMS + c4 + 2] = tf32r(v.z * qscale);
        sQ[r * SMS + c4 + 3] = tf32r(v.w * qscale);
    }

    float4 rk[8];
    // LDG K(0)
#pragma unroll
    for (int i = 0; i < 8; i++) {
        int f = tid + i * 256;
        int r = f >> 5, c4 = (f & 31) * 4;
        rk[i] = *reinterpret_cast<const float4*>(&Kbh[(size_t)r * DHEAD + c4]);
    }
    // V(0) prefetch
#pragma unroll
    for (int i = 0; i < 16; i++) {
        int f = tid + i * 256;
        int r = f >> 5, c4 = (f & 31) * 4;
        cp_async16(svu + (uint32_t)(r * SVS + c4) * 4, &Vbh[(size_t)r * DHEAD + c4]);
    }
    asm volatile("cp.async.commit_group;\n");
    // STS K(0) -> sK0 (RNA)
#pragma unroll
    for (int i = 0; i < 8; i++) {
        int f = tid + i * 256;
        int r = f >> 5, c4 = (f & 31) * 4;
        float4 v;
        v.x = tf32r(rk[i].x); v.y = tf32r(rk[i].y);
        v.z = tf32r(rk[i].z); v.w = tf32r(rk[i].w);
        *reinterpret_cast<float4*>(&sK0[r * SMS + c4]) = v;
    }
    // LDG K(1)
#pragma unroll
    for (int i = 0; i < 8; i++) {
        int f = tid + i * 256;
        int r = f >> 5, c4 = (f & 31) * 4;
        rk[i] = *reinterpret_cast<const float4*>(&Kbh[(size_t)(64 + r) * DHEAD + c4]);
    }

    float m0 = -1e30f, m1 = -1e30f, l0 = 0.f, l1 = 0.f;
    float O[16][4];
#pragma unroll
    for (int nt = 0; nt < 16; nt++)
#pragma unroll
        for (int e = 0; e < 4; e++) O[nt][e] = 0.f;

    int srcA = 4 * g + (tg >> 1);
    int srcB = srcA + 2;
    bool oddt = (tg & 1) != 0;

    // ---- main loop over 34 subtiles of 64 keys ----
    for (int s = 0; s < 34; s++) {
        float* sKc = (s & 1) ? sK1 : sK0;

        // STS K(s+1) into the other buffer
        if (s < 33) {
            float* sKn = (s & 1) ? sK0 : sK1;
#pragma unroll
            for (int i = 0; i < 8; i++) {
                int f = tid + i * 256;
                int r = f >> 5, c4 = (f & 31) * 4;
                float4 v;
                v.x = tf32r(rk[i].x); v.y = tf32r(rk[i].y);
                v.z = tf32r(rk[i].z); v.w = tf32r(rk[i].w);
                *reinterpret_cast<float4*>(&sKn[r * SMS + c4]) = v;
            }
        }
        // LDG K(s+2)
        if (s < 32) {
#pragma unroll
            for (int i = 0; i < 8; i++) {
                int f = tid + i * 256;
                int r = f >> 5, c4 = (f & 31) * 4;
                rk[i] = *reinterpret_cast<const float4*>(
                    &Kbh[(size_t)((s + 2) * 64 + r) * DHEAD + c4]);
            }
        }
        if ((s & 1) == 0) asm volatile("cp.async.wait_group 0;\n");  // V(s/2) ready
        __syncthreads();

        // S = Q K_sub^T  (16 rows x 64 keys per warp)
        float S[8][4];
#pragma unroll
        for (int nt = 0; nt < 8; nt++)
#pragma unroll
            for (int e = 0; e < 4; e++) S[nt][e] = 0.f;

#pragma unroll
        for (int ks = 0; ks < 16; ks++) {
            float a[4];
            a[0] = sQ[(r0 + g) * SMS + ks * 8 + tg];
            a[1] = sQ[(r0 + g + 8) * SMS + ks * 8 + tg];
            a[2] = sQ[(r0 + g) * SMS + ks * 8 + tg + 4];
            a[3] = sQ[(r0 + g + 8) * SMS + ks * 8 + tg + 4];
#pragma unroll
            for (int nt = 0; nt < 8; nt++) {
                float bb[2];
                bb[0] = sKc[(nt * 8 + g) * SMS + ks * 8 + tg];
                bb[1] = sKc[(nt * 8 + g) * SMS + ks * 8 + tg + 4];
                mma8(S[nt], a, bb);
            }
        }

        // causal mask (new keys live in subtiles 32,33)
        if (s >= 32) {
            int cb = (s - 32) * 64;
            int q0 = r0 + g, q1 = q0 + 8;
#pragma unroll
            for (int nt = 0; nt < 8; nt++) {
                int c0 = cb + nt * 8 + 2 * tg;
                if (c0 > q0) S[nt][0] = -1e30f;
                if (c0 + 1 > q0) S[nt][1] = -1e30f;
                if (c0 > q1) S[nt][2] = -1e30f;
                if (c0 + 1 > q1) S[nt][3] = -1e30f;
            }
        }

        // online softmax over this 64-key slab
        float mx0 = -1e30f, mx1 = -1e30f;
#pragma unroll
        for (int nt = 0; nt < 8; nt++) {
            mx0 = fmaxf(mx0, fmaxf(S[nt][0], S[nt][1]));
            mx1 = fmaxf(mx1, fmaxf(S[nt][2], S[nt][3]));
        }
        mx0 = fmaxf(mx0, __shfl_xor_sync(0xffffffffu, mx0, 1));
        mx0 = fmaxf(mx0, __shfl_xor_sync(0xffffffffu, mx0, 2));
        mx1 = fmaxf(mx1, __shfl_xor_sync(0xffffffffu, mx1, 1));
        mx1 = fmaxf(mx1, __shfl_xor_sync(0xffffffffu, mx1, 2));

        float mn0 = fmaxf(m0, mx0), mn1 = fmaxf(m1, mx1);
        float sc0 = __expf(m0 - mn0), sc1 = __expf(m1 - mn1);
        float rs0 = 0.f, rs1 = 0.f;
#pragma unroll
        for (int nt = 0; nt < 8; nt++) {
            S[nt][0] = __expf(S[nt][0] - mn0);
            S[nt][1] = __expf(S[nt][1] - mn0);
            S[nt][2] = __expf(S[nt][2] - mn1);
            S[nt][3] = __expf(S[nt][3] - mn1);
            rs0 += S[nt][0] + S[nt][1];
            rs1 += S[nt][2] + S[nt][3];
        }
        rs0 += __shfl_xor_sync(0xffffffffu, rs0, 1);
        rs0 += __shfl_xor_sync(0xffffffffu, rs0, 2);
        rs1 += __shfl_xor_sync(0xffffffffu, rs1, 1);
        rs1 += __shfl_xor_sync(0xffffffffu, rs1, 2);

        l0 = l0 * sc0 + rs0;
        l1 = l1 * sc1 + rs1;
#pragma unroll
        for (int nt = 0; nt < 16; nt++) {
            O[nt][0] *= sc0; O[nt][1] *= sc0;
            O[nt][2] *= sc1; O[nt][3] *= sc1;
        }
        m0 = mn0; m1 = mn1;

        // round P for the MMA
#pragma unroll
        for (int nt = 0; nt < 8; nt++)
#pragma unroll
            for (int e = 0; e < 4; e++) S[nt][e] = tf32r(S[nt][e]);

        // O += P V : P acc-fragments -> A-fragments via shuffles
        int vrow0 = (s & 1) * 64;
#pragma unroll
        for (int kv = 0; kv < 8; kv++) {
            float e0 = __shfl_sync(0xffffffffu, S[kv][0], srcA);
            float o0 = __shfl_sync(0xffffffffu, S[kv][1], srcA);
            float e1 = __shfl_sync(0xffffffffu, S[kv][2], srcA);
            float o1 = __shfl_sync(0xffffffffu, S[kv][3], srcA);
            float f0 = __shfl_sync(0xffffffffu, S[kv][0], srcB);
            float p0 = __shfl_sync(0xffffffffu, S[kv][1], srcB);
            float f1 = __shfl_sync(0xffffffffu, S[kv][2], srcB);
            float p1 = __shfl_sync(0xffffffffu, S[kv][3], srcB);
            float a[4];
            a[0] = oddt ? o0 : e0;
            a[1] = oddt ? o1 : e1;
            a[2] = oddt ? p0 : f0;
            a[3] = oddt ? p1 : f1;
#pragma unroll
            for (int nt = 0; nt < 16; nt++) {
                float bb[2];
                bb[0] = sV[(vrow0 + kv * 8 + tg) * SVS + nt * 8 + g];
                bb[1] = sV[(vrow0 + kv * 8 + tg + 4) * SVS + nt * 8 + g];
                mma8(O[nt], a, bb);
            }
        }

        __syncthreads();  // all warps done with sK[s&1] and (if s odd) sV

        // refill V for the next tile-pair
        if ((s & 1) == 1 && s < 33) {
            int vt = (s >> 1) + 1;
#pragma unroll
            for (int i = 0; i < 16; i++) {
                int f = tid + i * 256;
                int r = f >> 5, c4 = (f & 31) * 4;
                cp_async16(svu + (uint32_t)(r * SVS + c4) * 4,
                           &Vbh[(size_t)(vt * 128 + r) * DHEAD + c4]);
            }
            asm volatile("cp.async.commit_group;\n");
        }
    }

    float i0 = 1.f / l0, i1 = 1.f / l1;
#pragma unroll
    for (int nt = 0; nt < 16; nt++) {
        int col = h * DHEAD + nt * 8 + 2 * tg;
        float* o0 = &g_attn[(size_t)(b * TNEW + r0 + g) * CDIM + col];
        o0[0] = tf32r(O[nt][0] * i0);
        o0[1] = tf32r(O[nt][1] * i0);
        float* o1 = &g_attn[(size_t)(b * TNEW + r0 + g + 8) * CDIM + col];
        o1[0] = tf32r(O[nt][2] * i1);
        o1[1] = tf32r(O[nt][3] * i1);
    }
}

// ---------------------------------------------------------------------------
extern "C" void kernel_launch(void* const* d_in, const int* in_sizes, int n_in,
                              void* d_out, int out_size)
{
    const float* x  = (const float*)d_in[0];
    const float* Kp = (const float*)d_in[1];
    const float* Vp = (const float*)d_in[2];
    const float* Wq = (const float*)d_in[3];
    const float* bq = (const float*)d_in[4];
    const float* Wk = (const float*)d_in[5];
    const float* bk = (const float*)d_in[6];
    const float* Wv = (const float*)d_in[7];
    const float* bv = (const float*)d_in[8];
    const float* Wo = (const float*)d_in[9];
    const float* bo = (const float*)d_in[10];

    float* out  = (float*)d_out;
    float* Kout = out + (size_t)M_ROWS * CDIM;
    float* Vout = Kout + (size_t)BATCH * HHEADS * TTOT * DHEAD;

    float* gQ;
    cudaGetSymbolAddress((void**)&gQ, g_Q);

    cudaFuncSetAttribute(attn_kernel, cudaFuncAttributeMaxDynamicSharedMemorySize, ATTN_SMEM_BYTES);
    cudaFuncSetAttribute(fused_qkv_copy, cudaFuncAttributeMaxDynamicSharedMemorySize, GEMM_SMEM_BYTES);
    cudaFuncSetAttribute(gemm_wo, cudaFuncAttributeMaxDynamicSharedMemorySize, GEMM_SMEM_BYTES);

    // Phase 0: transpose+round weights, round x, init out with bias
    prep_kernel<<<dim3(64, 64, 6), dim3(32, 8)>>>(Wq, Wk, Wv, Wo, x, bo, out);

    // Phase 1: fused QKV GEMMs + past-KV copy (role-interleaved)
    fused_qkv_copy<<<512, 256, GEMM_SMEM_BYTES>>>(bq, bk, bv, Kp, Vp, gQ, Kout, Vout);

    // Phase 2: attention
    attn_kernel<<<BATCH * HHEADS, 256, ATTN_SMEM_BYTES>>>(Kout, Vout);

    // Phase 3: output projection (split-K x2, deterministic RED.ADD)
    gemm_wo<<<256, 256, GEMM_SMEM_BYTES>>>(out);
}

// round 15
// speedup vs baseline: 1.2484x; 1.0380x over previous
#include <cuda_runtime.h>
#include <cuda_bf16.h>
#include <cstdint>

// Problem constants (fixed by the dataset)
#define M_ROWS 1024     // B*T_NEW
#define CDIM   2048
#define HHEADS 16
#define DHEAD  128
#define TPAST  2048
#define TNEW   128
#define TTOT   2176
#define BATCH  8

// ---------------------------------------------------------------------------
// Scratch (no cudaMalloc allowed)
// ---------------------------------------------------------------------------
__device__ float g_Q[M_ROWS * CDIM];       // 8 MB
__device__ float g_attn[M_ROWS * CDIM];    // 8 MB (tf32-pre-rounded by attn)
__device__ float g_xr[M_ROWS * CDIM];      // 8 MB  x, tf32-pre-rounded
__device__ float g_WT[4ull * CDIM * CDIM]; // 64 MB Wq/Wk/Wv/Wo transposed+rounded

__device__ __forceinline__ float tf32r(float x) {
    float y;
    asm("cvt.rna.tf32.f32 %0, %1;" : "=f"(y) : "f"(x));
    return y;
}
__device__ __forceinline__ void mma8(float* c, const float* a, const float* b) {
    const uint32_t* A = reinterpret_cast<const uint32_t*>(a);
    const uint32_t* B = reinterpret_cast<const uint32_t*>(b);
    asm volatile(
        "mma.sync.aligned.m16n8k8.row.col.f32.tf32.tf32.f32 "
        "{%0,%1,%2,%3}, {%4,%5,%6,%7}, {%8,%9}, {%0,%1,%2,%3};\n"
        : "+f"(c[0]), "+f"(c[1]), "+f"(c[2]), "+f"(c[3])
        : "r"(A[0]), "r"(A[1]), "r"(A[2]), "r"(A[3]), "r"(B[0]), "r"(B[1]));
}
__device__ __forceinline__ void cp_async16(uint32_t saddr, const void* gaddr) {
    asm volatile("cp.async.ca.shared.global [%0], [%1], 16;\n" :: "r"(saddr), "l"(gaddr));
}
#define SWZ128(o) ((o) ^ (((o) >> 3) & 0x70))

// ---------------------------------------------------------------------------
// Prep kernel: z<4 -> transpose+round W_z into g_WT slab; z==4 -> round x;
// z==5 -> init out with bias (for split-K RED.ADD epilogue of gemm_wo)
// grid (64,64,6), block (32,8)
// ---------------------------------------------------------------------------
__global__ void prep_kernel(
    const float* __restrict__ Wq, const float* __restrict__ Wk,
    const float* __restrict__ Wv, const float* __restrict__ Wo,
    const float* __restrict__ x, const float* __restrict__ bo,
    float* __restrict__ out)
{
    int z = blockIdx.z;
    int tx = threadIdx.x, ty = threadIdx.y;
    if (z >= 4) {
        int idx = blockIdx.y * 64 + blockIdx.x;
        if (idx >= 1024) return;
        size_t base = (size_t)idx * 2048 + (ty * 32 + tx) * 8;
        if (z == 4) {
            const float4* src = reinterpret_cast<const float4*>(x + base);
            float4* dst = reinterpret_cast<float4*>(g_xr + base);
#pragma unroll
            for (int j = 0; j < 2; j++) {
                float4 v = src[j];
                v.x = tf32r(v.x); v.y = tf32r(v.y); v.z = tf32r(v.z); v.w = tf32r(v.w);
                dst[j] = v;
            }
        } else {
            const float4* bsrc = reinterpret_cast<const float4*>(bo + (base & (CDIM - 1)));
            float4* dst = reinterpret_cast<float4*>(out + base);
#pragma unroll
            for (int j = 0; j < 2; j++) dst[j] = bsrc[j];
        }
        return;
    }
    const float* W = (z == 0) ? Wq : (z == 1) ? Wk : (z == 2) ? Wv : Wo;
    float* WT = g_WT + (size_t)z * CDIM * CDIM;
    __shared__ float t[32][33];
    int x0 = blockIdx.x * 32, y0 = blockIdx.y * 32;
#pragma unroll
    for (int j = 0; j < 4; j++)
        t[ty + 8 * j][tx] = tf32r(W[(size_t)(y0 + ty + 8 * j) * CDIM + x0 + tx]);
    __syncthreads();
#pragma unroll
    for (int j = 0; j < 4; j++)
        WT[(size_t)(x0 + ty + 8 * j) * CDIM + y0 + tx] = t[tx][ty + 8 * j];
}

// ---------------------------------------------------------------------------
// cp.async 2-stage tf32 GEMM (best measured config): CTA 128x128,
// warp 64x32, k-chunk 32.  smem: 2 stages x 32 KB = 64 KB -> 2 CTAs/SM.
// ---------------------------------------------------------------------------
#define GSTAGE_FLOATS 8192            // 32 KB per stage (A 4096 + B 4096)
#define GEMM_SMEM_BYTES (2 * GSTAGE_FLOATS * 4)   // 65536

__device__ __forceinline__ void fill_chunk(
    uint32_t sbase, int st, const float* __restrict__ Ap,
    const float* __restrict__ Bp, int kt)
{
    uint32_t base = sbase + st * (GSTAGE_FLOATS * 4);
    int tid = threadIdx.x;
#pragma unroll
    for (int i = 0; i < 4; i++) {
        int f = tid + i * 256;            // 0..1023
        int r = f >> 3, k4 = f & 7;
        uint32_t off = SWZ128((uint32_t)(r * 128 + k4 * 16));
        cp_async16(base + off,         Ap + (size_t)r * CDIM + kt + k4 * 4);
        cp_async16(base + 16384 + off, Bp + (size_t)r * CDIM + kt + k4 * 4);
    }
    asm volatile("cp.async.commit_group;\n");
}

__device__ __forceinline__ void gemm_core(
    const float* __restrict__ Ap, const float* __restrict__ Bp,
    const float* __restrict__ bias, float* __restrict__ out,
    int scatter, int bm, int bn, float* smem, int k0, int kch, int red)
{
    int tid = threadIdx.x;
    int lane = tid & 31, wid = tid >> 5;
    int g = lane >> 2, tg = lane & 3;
    int wr = (wid >> 2) * 64;
    int wc = (wid & 3) * 32;
    uint32_t sbase = (uint32_t)__cvta_generic_to_shared(smem);

    float acc[4][4][4];
#pragma unroll
    for (int i = 0; i < 4; i++)
#pragma unroll
        for (int j = 0; j < 4; j++)
#pragma unroll
            for (int k = 0; k < 4; k++) acc[i][j][k] = 0.f;

    fill_chunk(sbase, 0, Ap, Bp, k0);
    fill_chunk(sbase, 1, Ap, Bp, k0 + 32);
    asm volatile("cp.async.wait_group 1;\n");
    __syncthreads();

    int xv = g << 2;

    for (int i = 0; i < kch; i++) {
        int st = i & 1;
        const float* sA = smem + st * GSTAGE_FLOATS;
        const float* sB = sA + 4096;

#pragma unroll
        for (int ks = 0; ks < 4; ks++) {
            int c0 = (ks * 8 + tg) ^ xv;
            int c1 = (ks * 8 + tg + 4) ^ xv;
            float a[4][4];
#pragma unroll
            for (int mi = 0; mi < 4; mi++) {
                int r0 = (wr + mi * 16 + g) * 32;
                int r1 = r0 + 8 * 32;
                a[mi][0] = sA[r0 + c0];
                a[mi][1] = sA[r1 + c0];
                a[mi][2] = sA[r0 + c1];
                a[mi][3] = sA[r1 + c1];
            }
            float b[4][2];
#pragma unroll
            for (int ni = 0; ni < 4; ni++) {
                int rn = (wc + ni * 8 + g) * 32;
                b[ni][0] = sB[rn + c0];
                b[ni][1] = sB[rn + c1];
            }
#pragma unroll
            for (int mi = 0; mi < 4; mi++)
#pragma unroll
                for (int ni = 0; ni < 4; ni++)
                    mma8(acc[mi][ni], a[mi], b[ni]);
        }

        __syncthreads();
        if (i + 2 < kch) fill_chunk(sbase, st, Ap, Bp, k0 + (i + 2) * 32);
        if (i + 1 < kch) {
            if (i + 2 < kch) asm volatile("cp.async.wait_group 1;\n");
            else             asm volatile("cp.async.wait_group 0;\n");
            __syncthreads();
        }
    }

#pragma unroll
    for (int mi = 0; mi < 4; mi++) {
#pragma unroll
        for (int ni = 0; ni < 4; ni++) {
            int row0 = bm + wr + mi * 16 + g;
            int col0 = bn + wc + ni * 8 + 2 * tg;
#pragma unroll
            for (int e = 0; e < 4; e++) {
                int row = row0 + ((e >= 2) ? 8 : 0);
                int col = col0 + (e & 1);
                float v = acc[mi][ni][e];
                if (red) {
                    atomicAdd(&out[(size_t)row * CDIM + col], v);
                } else if (!scatter) {
                    out[(size_t)row * CDIM + col] = v + bias[col];
                } else {
                    int b_ = row >> 7, t_ = row & 127;
                    int h_ = col >> 7, d_ = col & 127;
                    out[((size_t)(b_ * HHEADS + h_) * TTOT + TPAST + t_) * DHEAD + d_] = v + bias[col];
                }
            }
        }
    }
}

// ---------------------------------------------------------------------------
// Fused: 512 CTAs; role = bid&3 (0=Q,1=K,2=V GEMM, 3=past copy)
// ---------------------------------------------------------------------------
__global__ __launch_bounds__(256, 2) void fused_qkv_copy(
    const float* __restrict__ bq, const float* __restrict__ bk, const float* __restrict__ bv,
    const float* __restrict__ Kp, const float* __restrict__ Vp,
    float* __restrict__ gQ, float* __restrict__ Kout, float* __restrict__ Vout)
{
    extern __shared__ __align__(16) float smem[];
    int lin = blockIdx.x;
    int role = lin & 3;
    int t = lin >> 2;  // 0..127

    if (role == 3) {
        const float4* Ks = reinterpret_cast<const float4*>(Kp) + (size_t)t * (TPAST * DHEAD / 4);
        const float4* Vs = reinterpret_cast<const float4*>(Vp) + (size_t)t * (TPAST * DHEAD / 4);
        float4* Kd = reinterpret_cast<float4*>(Kout) + (size_t)t * (TTOT * DHEAD / 4);
        float4* Vd = reinterpret_cast<float4*>(Vout) + (size_t)t * (TTOT * DHEAD / 4);
        for (int i = threadIdx.x; i < TPAST * DHEAD / 4; i += 256) {
            Kd[i] = Ks[i];
            Vd[i] = Vs[i];
        }
        return;
    }

    int bm = (t >> 4) * 128, bn = (t & 15) * 128;
    const float* Ap = g_xr + (size_t)bm * CDIM;
    const float* Bp = g_WT + (size_t)role * CDIM * CDIM + (size_t)bn * CDIM;
    if (role == 0)      gemm_core(Ap, Bp, bq, gQ,   0, bm, bn, smem, 0, 64, 0);
    else if (role == 1) gemm_core(Ap, Bp, bk, Kout, 1, bm, bn, smem, 0, 64, 0);
    else                gemm_core(Ap, Bp, bv, Vout, 1, bm, bn, smem, 0, 64, 0);
}

// gemm_wo split-K x2: 256 CTAs; tile = bid>>1, kslice = bid&1; RED.ADD epilogue
__global__ __launch_bounds__(256, 2) void gemm_wo(float* __restrict__ out)
{
    extern __shared__ __align__(16) float smem[];
    int t = blockIdx.x;
    int tile = t >> 1, ksl = t & 1;
    int bm = (tile >> 4) * 128, bn = (tile & 15) * 128;
    gemm_core(g_attn + (size_t)bm * CDIM,
              g_WT + 3ull * CDIM * CDIM + (size_t)bn * CDIM,
              nullptr, out, 0, bm, bn, smem, ksl * 1024, 32, 1);
}

// ---------------------------------------------------------------------------
// Flash attention: one CTA per (b,h), 8 warps x 16 query rows.
// Q: fragments hoisted to registers (qa[16][4], loaded once).
// K: 64-row subtiles double-buffered, register-staged (LDG -> RNA -> STS),
//    stored in PERMUTED-k layout (k -> (k&~7) + ((k&3)<<1) + ((k>>2)&1))
//    at stride SKS=136 so b-fragments are conflict-free LDS.64.
// V: cp.async (raw), 1 tile ahead, stride SVS=136 (conflict-free PV loads).
// P in registers via shuffles.  Softmax per 64-key slab.
// smem = sK0(64)+sK1(64)+sV(128), all @136 = 139,264 B.
// ---------------------------------------------------------------------------
#define SKS 136  // sK row stride: perm LDS.64 bank-pair = 4g+tg, conflict-free
#define SVS 136  // sV row stride: PV banks 8tg+g, conflict-free
#define ATTN_SMEM_BYTES (256 * 136 * 4)   // 139264

__global__ __launch_bounds__(256) void attn_kernel(
    const float* __restrict__ Kc, const float* __restrict__ Vc)
{
    extern __shared__ float sm[];
    float* sK0 = sm;                        // 64 rows @ SKS (permuted k)
    float* sK1 = sm + 64 * SKS;             // 64 rows @ SKS (permuted k)
    float* sV  = sm + 128 * SKS;            // 128 rows @ SVS

    int tid = threadIdx.x, lane = tid & 31, wid = tid >> 5;
    int g = lane >> 2, tg = lane & 3;
    int bh = blockIdx.x, b = bh >> 4, h = bh & 15;
    const float qscale = 0.08838834764831845f;  // 1/sqrt(128)

    uint32_t svu = (uint32_t)__cvta_generic_to_shared(sV);

    const float* Kbh = Kc + (size_t)bh * TTOT * DHEAD;
    const float* Vbh = Vc + (size_t)bh * TTOT * DHEAD;

    int r0 = wid * 16;

    // ---- prologue ----
    float4 rk[8];
    // LDG K(0)
#pragma unroll
    for (int i = 0; i < 8; i++) {
        int f = tid + i * 256;
        int r = f >> 5, c4 = (f & 31) * 4;
        rk[i] = *reinterpret_cast<const float4*>(&Kbh[(size_t)r * DHEAD + c4]);
    }
    // V(0) prefetch
#pragma unroll
    for (int i = 0; i < 16; i++) {
        int f = tid + i * 256;
        int r = f >> 5, c4 = (f & 31) * 4;
        cp_async16(svu + (uint32_t)(r * SVS + c4) * 4, &Vbh[(size_t)r * DHEAD + c4]);
    }
    asm volatile("cp.async.commit_group;\n");

    // Q fragments -> registers (scaled, RNA tf32); reused across all subtiles
    float qa[16][4];
    {
        const float* q0 = g_Q + (size_t)(b * TNEW + r0 + g) * CDIM + h * DHEAD;
        const float* q1 = q0 + 8 * CDIM;
#pragma unroll
        for (int ks = 0; ks < 16; ks++) {
            qa[ks][0] = tf32r(q0[ks * 8 + tg] * qscale);
            qa[ks][1] = tf32r(q1[ks * 8 + tg] * qscale);
            qa[ks][2] = tf32r(q0[ks * 8 + tg + 4] * qscale);
            qa[ks][3] = tf32r(q1[ks * 8 + tg + 4] * qscale);
        }
    }

    // STS K(0) -> sK0 (RNA, permuted k)
#pragma unroll
    for (int i = 0; i < 8; i++) {
        int f = tid + i * 256;
        int r = f >> 5, c4 = (f & 31) * 4;
        float v[4] = {tf32r(rk[i].x), tf32r(rk[i].y), tf32r(rk[i].z), tf32r(rk[i].w)};
#pragma unroll
        for (int j = 0; j < 4; j++) {
            int k = c4 + j;
            int p = (k & ~7) + ((k & 3) << 1) + ((k >> 2) & 1);
            sK0[r * SKS + p] = v[j];
        }
    }
    // LDG K(1)
#pragma unroll
    for (int i = 0; i < 8; i++) {
        int f = tid + i * 256;
        int r = f >> 5, c4 = (f & 31) * 4;
        rk[i] = *reinterpret_cast<const float4*>(&Kbh[(size_t)(64 + r) * DHEAD + c4]);
    }

    float m0 = -1e30f, m1 = -1e30f, l0 = 0.f, l1 = 0.f;
    float O[16][4];
#pragma unroll
    for (int nt = 0; nt < 16; nt++)
#pragma unroll
        for (int e = 0; e < 4; e++) O[nt][e] = 0.f;

    int srcA = 4 * g + (tg >> 1);
    int srcB = srcA + 2;
    bool oddt = (tg & 1) != 0;

    // ---- main loop over 34 subtiles of 64 keys ----
    for (int s = 0; s < 34; s++) {
        float* sKc = (s & 1) ? sK1 : sK0;

        // STS K(s+1) into the other buffer (permuted k)
        if (s < 33) {
            float* sKn = (s & 1) ? sK0 : sK1;
#pragma unroll
            for (int i = 0; i < 8; i++) {
                int f = tid + i * 256;
                int r = f >> 5, c4 = (f & 31) * 4;
                float v[4] = {tf32r(rk[i].x), tf32r(rk[i].y), tf32r(rk[i].z), tf32r(rk[i].w)};
#pragma unroll
                for (int j = 0; j < 4; j++) {
                    int k = c4 + j;
                    int p = (k & ~7) + ((k & 3) << 1) + ((k >> 2) & 1);
                    sKn[r * SKS + p] = v[j];
                }
            }
        }
        // LDG K(s+2)
        if (s < 32) {
#pragma unroll
            for (int i = 0; i < 8; i++) {
                int f = tid + i * 256;
                int r = f >> 5, c4 = (f & 31) * 4;
                rk[i] = *reinterpret_cast<const float4*>(
                    &Kbh[(size_t)((s + 2) * 64 + r) * DHEAD + c4]);
            }
        }
        if ((s & 1) == 0) asm volatile("cp.async.wait_group 0;\n");  // V(s/2) ready
        __syncthreads();

        // S = Q K_sub^T  (16 rows x 64 keys per warp); b-frags are LDS.64
        float S[8][4];
#pragma unroll
        for (int nt = 0; nt < 8; nt++)
#pragma unroll
            for (int e = 0; e < 4; e++) S[nt][e] = 0.f;

#pragma unroll
        for (int ks = 0; ks < 16; ks++) {
#pragma unroll
            for (int nt = 0; nt < 8; nt++) {
                float2 bb = *reinterpret_cast<const float2*>(
                    &sKc[(nt * 8 + g) * SKS + ks * 8 + 2 * tg]);
                float bv[2] = {bb.x, bb.y};
                mma8(S[nt], qa[ks], bv);
            }
        }

        // causal mask (new keys live in subtiles 32,33)
        if (s >= 32) {
            int cb = (s - 32) * 64;
            int q0r = r0 + g, q1r = q0r + 8;
#pragma unroll
            for (int nt = 0; nt < 8; nt++) {
                int c0 = cb + nt * 8 + 2 * tg;
                if (c0 > q0r) S[nt][0] = -1e30f;
                if (c0 + 1 > q0r) S[nt][1] = -1e30f;
                if (c0 > q1r) S[nt][2] = -1e30f;
                if (c0 + 1 > q1r) S[nt][3] = -1e30f;
            }
        }

        // online softmax over this 64-key slab
        float mx0 = -1e30f, mx1 = -1e30f;
#pragma unroll
        for (int nt = 0; nt < 8; nt++) {
            mx0 = fmaxf(mx0, fmaxf(S[nt][0], S[nt][1]));
            mx1 = fmaxf(mx1, fmaxf(S[nt][2], S[nt][3]));
        }
        mx0 = fmaxf(mx0, __shfl_xor_sync(0xffffffffu, mx0, 1));
        mx0 = fmaxf(mx0, __shfl_xor_sync(0xffffffffu, mx0, 2));
        mx1 = fmaxf(mx1, __shfl_xor_sync(0xffffffffu, mx1, 1));
        mx1 = fmaxf(mx1, __shfl_xor_sync(0xffffffffu, mx1, 2));

        float mn0 = fmaxf(m0, mx0), mn1 = fmaxf(m1, mx1);
        float sc0 = __expf(m0 - mn0), sc1 = __expf(m1 - mn1);
        float rs0 = 0.f, rs1 = 0.f;
#pragma unroll
        for (int nt = 0; nt < 8; nt++) {
            S[nt][0] = __expf(S[nt][0] - mn0);
            S[nt][1] = __expf(S[nt][1] - mn0);
            S[nt][2] = __expf(S[nt][2] - mn1);
            S[nt][3] = __expf(S[nt][3] - mn1);
            rs0 += S[nt][0] + S[nt][1];
            rs1 += S[nt][2] + S[nt][3];
        }
        rs0 += __shfl_xor_sync(0xffffffffu, rs0, 1);
        rs0 += __shfl_xor_sync(0xffffffffu, rs0, 2);
        rs1 += __shfl_xor_sync(0xffffffffu, rs1, 1);
        rs1 += __shfl_xor_sync(0xffffffffu, rs1, 2);

        l0 = l0 * sc0 + rs0;
        l1 = l1 * sc1 + rs1;
#pragma unroll
        for (int nt = 0; nt < 16; nt++) {
            O[nt][0] *= sc0; O[nt][1] *= sc0;
            O[nt][2] *= sc1; O[nt][3] *= sc1;
        }
        m0 = mn0; m1 = mn1;

        // round P for the MMA
#pragma unroll
        for (int nt = 0; nt < 8; nt++)
#pragma unroll
            for (int e = 0; e < 4; e++) S[nt][e] = tf32r(S[nt][e]);

        // O += P V : P acc-fragments -> A-fragments via shuffles
        int vrow0 = (s & 1) * 64;
#pragma unroll
        for (int kv = 0; kv < 8; kv++) {
            float e0 = __shfl_sync(0xffffffffu, S[kv][0], srcA);
            float o0 = __shfl_sync(0xffffffffu, S[kv][1], srcA);
            float e1 = __shfl_sync(0xffffffffu, S[kv][2], srcA);
            float o1 = __shfl_sync(0xffffffffu, S[kv][3], srcA);
            float f0 = __shfl_sync(0xffffffffu, S[kv][0], srcB);
            float p0 = __shfl_sync(0xffffffffu, S[kv][1], srcB);
            float f1 = __shfl_sync(0xffffffffu, S[kv][2], srcB);
            float p1 = __shfl_sync(0xffffffffu, S[kv][3], srcB);
            float a[4];
            a[0] = oddt ? o0 : e0;
            a[1] = oddt ? o1 : e1;
            a[2] = oddt ? p0 : f0;
            a[3] = oddt ? p1 : f1;
#pragma unroll
            for (int nt = 0; nt < 16; nt++) {
                float bb[2];
                bb[0] = sV[(vrow0 + kv * 8 + tg) * SVS + nt * 8 + g];
                bb[1] = sV[(vrow0 + kv * 8 + tg + 4) * SVS + nt * 8 + g];
                mma8(O[nt], a, bb);
            }
        }

        __syncthreads();  // all warps done with sK[s&1] and (if s odd) sV

        // refill V for the next tile-pair
        if ((s & 1) == 1 && s < 33) {
            int vt = (s >> 1) + 1;
#pragma unroll
            for (int i = 0; i < 16; i++) {
                int f = tid + i * 256;
                int r = f >> 5, c4 = (f & 31) * 4;
                cp_async16(svu + (uint32_t)(r * SVS + c4) * 4,
                           &Vbh[(size_t)(vt * 128 + r) * DHEAD + c4]);
            }
            asm volatile("cp.async.commit_group;\n");
        }
    }

    float i0 = 1.f / l0, i1 = 1.f / l1;
#pragma unroll
    for (int nt = 0; nt < 16; nt++) {
        int col = h * DHEAD + nt * 8 + 2 * tg;
        float* o0 = &g_attn[(size_t)(b * TNEW + r0 + g) * CDIM + col];
        o0[0] = tf32r(O[nt][0] * i0);
        o0[1] = tf32r(O[nt][1] * i0);
        float* o1 = &g_attn[(size_t)(b * TNEW + r0 + g + 8) * CDIM + col];
        o1[0] = tf32r(O[nt][2] * i1);
        o1[1] = tf32r(O[nt][3] * i1);
    }
}

// ---------------------------------------------------------------------------
extern "C" void kernel_launch(void* const* d_in, const int* in_sizes, int n_in,
                              void* d_out, int out_size)
{
    const float* x  = (const float*)d_in[0];
    const float* Kp = (const float*)d_in[1];
    const float* Vp = (const float*)d_in[2];
    const float* Wq = (const float*)d_in[3];
    const float* bq = (const float*)d_in[4];
    const float* Wk = (const float*)d_in[5];
    const float* bk = (const float*)d_in[6];
    const float* Wv = (const float*)d_in[7];
    const float* bv = (const float*)d_in[8];
    const float* Wo = (const float*)d_in[9];
    const float* bo = (const float*)d_in[10];

    float* out  = (float*)d_out;
    float* Kout = out + (size_t)M_ROWS * CDIM;
    float* Vout = Kout + (size_t)BATCH * HHEADS * TTOT * DHEAD;

    float* gQ;
    cudaGetSymbolAddress((void**)&gQ, g_Q);

    cudaFuncSetAttribute(attn_kernel, cudaFuncAttributeMaxDynamicSharedMemorySize, ATTN_SMEM_BYTES);
    cudaFuncSetAttribute(fused_qkv_copy, cudaFuncAttributeMaxDynamicSharedMemorySize, GEMM_SMEM_BYTES);
    cudaFuncSetAttribute(gemm_wo, cudaFuncAttributeMaxDynamicSharedMemorySize, GEMM_SMEM_BYTES);

    // Phase 0: transpose+round weights, round x, init out with bias
    prep_kernel<<<dim3(64, 64, 6), dim3(32, 8)>>>(Wq, Wk, Wv, Wo, x, bo, out);

    // Phase 1: fused QKV GEMMs + past-KV copy (role-interleaved)
    fused_qkv_copy<<<512, 256, GEMM_SMEM_BYTES>>>(bq, bk, bv, Kp, Vp, gQ, Kout, Vout);

    // Phase 2: attention
    attn_kernel<<<BATCH * HHEADS, 256, ATTN_SMEM_BYTES>>>(Kout, Vout);

    // Phase 3: output projection (split-K x2, deterministic RED.ADD)
    gemm_wo<<<256, 256, GEMM_SMEM_BYTES>>>(out);
}